// round 2
// baseline (speedup 1.0000x reference)
#include <cuda_runtime.h>
#include <math.h>

// ---------------- problem constants ----------------
#define NB   16      // b*m images for global path
#define D    256
#define NH   8
#define HD   32
#define NTOK 98      // m*w*w = 2*7*7
#define NWIN 512     // b*gx*gy
#define SEH  64
#define H1   56
#define H2   28
#define H3   14
#define MROWS 50176  // NWIN*NTOK

// ---------------- scratch (device globals, no allocs) ----------------
__device__ float g_xg0[NB*D*H1*H1];
__device__ float g_y  [NB*D*H1*H1];
__device__ float g_z  [NB*D*H1*H1];
__device__ float g_xg1[NB*D*H2*H2];
__device__ float g_xg2[NB*D*H3*H3];
__device__ float g_smean[NB*D];
__device__ float g_svec [NB*D];
__device__ float g_gout [8*4*NTOK*D];
__device__ float g_qglob[8*NTOK*D];
__device__ float g_kv   [(size_t)NWIN*NTOK*2*D];
__device__ float g_biasb[NH*NTOK*NTOK];
__device__ float g_aout [(size_t)NWIN*NTOK*D];

__device__ __forceinline__ float gelu_f(float v){
    return 0.5f*v*(1.0f+erff(v*0.70710678118654752440f));
}

// x-layout row offset for (win, token): identical for input x and final output
__device__ __forceinline__ long xrow_off(int r){
    int win=r/NTOK, i=r%NTOK;
    int b=win>>6, gx=(win>>3)&7, gy=win&7;
    int m=i/49, rr=i%49, w1=rr/7, w2=rr%7;
    return (((((long)(b*2+m)*8+gx)*8+gy)*7+w1)*7+w2)*256;
}

// ---------------- 1. rearrange x -> (b*m, d, 56, 56) ----------------
__global__ void k_rearrange(const float* __restrict__ x){
    int o=blockIdx.x*blockDim.x+threadIdx.x;
    if(o>=NB*D*H1*H1) return;
    int Wp=o%H1; int t=o/H1;
    int Hp=t%H1; t/=H1;
    int c=t%D;   int n=t/D;
    int b=n>>1, m=n&1;
    int gx=Hp/7, w1=Hp%7;
    int gy=Wp/7, w2=Wp%7;
    long off=(((((long)(b*2+m)*8+gx)*8+gy)*7+w1)*7+w2)*256 + c;
    g_xg0[o]=x[off];
}

// ---------------- 2. depthwise 3x3 conv (pad 1) + exact GELU ----------------
__global__ void k_dwconv_gelu(const float* __restrict__ in, const float* __restrict__ dw,
                              float* __restrict__ out, int HW){
    int o=blockIdx.x*blockDim.x+threadIdx.x;
    int total=NB*D*HW*HW;
    if(o>=total) return;
    int wx=o%HW; int t=o/HW;
    int hy=t%HW; t/=HW;          // t = n*D + c
    int c=t%D;
    const float* ip = in + (long)t*HW*HW;
    const float* wp = dw + c*9;
    float acc=0.f;
    #pragma unroll
    for(int kh=0;kh<3;kh++){
        int hh=hy+kh-1;
        if(hh<0||hh>=HW) continue;
        #pragma unroll
        for(int kw=0;kw<3;kw++){
            int ww=wx+kw-1;
            if(ww<0||ww>=HW) continue;
            acc += ip[hh*HW+ww]*wp[kh*3+kw];
        }
    }
    out[o]=gelu_f(acc);
}

// ---------------- 3. mean over HW per (n,c) ----------------
__global__ void k_hwmean(const float* __restrict__ y, float* __restrict__ sm, int HW){
    int nc=blockIdx.x;
    const float* p = y + (long)nc*HW*HW;
    float s=0.f;
    for(int i=threadIdx.x;i<HW*HW;i+=blockDim.x) s+=p[i];
    __shared__ float red[256];
    red[threadIdx.x]=s; __syncthreads();
    for(int st=128;st>0;st>>=1){
        if(threadIdx.x<st) red[threadIdx.x]+=red[threadIdx.x+st];
        __syncthreads();
    }
    if(threadIdx.x==0) sm[nc]=red[0]/(float)(HW*HW);
}

// ---------------- 4. SE MLP: sigmoid(gelu(s@se1)@se2) ----------------
__global__ void k_se(const float* __restrict__ sm, const float* __restrict__ se1,
                     const float* __restrict__ se2, float* __restrict__ sv){
    int n=blockIdx.x;
    __shared__ float sin_[D];
    __shared__ float hid[SEH];
    int t=threadIdx.x;            // 256 threads
    sin_[t]=sm[n*D+t];
    __syncthreads();
    if(t<SEH){
        float a=0.f;
        for(int c=0;c<D;c++) a+=sin_[c]*se1[c*SEH+t];
        hid[t]=gelu_f(a);
    }
    __syncthreads();
    float a=0.f;
    for(int j=0;j<SEH;j++) a+=hid[j]*se2[j*D+t];
    sv[n*D+t]=1.f/(1.f+expf(-a));
}

// ---------------- 5. pointwise conv (SE scale fused into A-tile) ----------------
// z[n,co,p] = sum_ci pw[co,ci]*sv[n,ci]*y[n,ci,p]
__global__ void k_pwconv(const float* __restrict__ pw, const float* __restrict__ y,
                         const float* __restrict__ sv, float* __restrict__ z, int P){
    __shared__ float As[16][65];
    __shared__ float Bs[16][65];
    int n=blockIdx.z;
    int co0=blockIdx.y*64;
    int p0 =blockIdx.x*64;
    int tid=threadIdx.x;
    int ty=tid>>4, tx=tid&15;
    const float* yb = y + (long)n*D*P;
    float acc[4][4]={};
    for(int k0=0;k0<D;k0+=16){
        #pragma unroll
        for(int l=0;l<4;l++){
            int e=tid+l*256; int kk=e&15, mm=e>>4;
            As[kk][mm]=pw[(co0+mm)*D + k0+kk]*sv[n*D+k0+kk];
        }
        #pragma unroll
        for(int l=0;l<4;l++){
            int e=tid+l*256; int nn=e&63, kk=e>>6;
            int p=p0+nn;
            Bs[kk][nn]=(p<P)? yb[(long)(k0+kk)*P+p] : 0.f;
        }
        __syncthreads();
        #pragma unroll
        for(int kk=0;kk<16;kk++){
            float a[4],b[4];
            #pragma unroll
            for(int i=0;i<4;i++) a[i]=As[kk][ty*4+i];
            #pragma unroll
            for(int j=0;j<4;j++) b[j]=Bs[kk][tx*4+j];
            #pragma unroll
            for(int i=0;i<4;i++)
                #pragma unroll
                for(int j=0;j<4;j++) acc[i][j]+=a[i]*b[j];
        }
        __syncthreads();
    }
    float* zb = z + (long)n*D*P;
    #pragma unroll
    for(int i=0;i<4;i++){
        int co=co0+ty*4+i;
        #pragma unroll
        for(int j=0;j<4;j++){
            int p=p0+tx*4+j;
            if(p<P) zb[(long)co*P+p]=acc[i][j];
        }
    }
}

// ---------------- 6. residual add + maxpool 3x3 s2 p1 ----------------
__global__ void k_respool(const float* __restrict__ xin, const float* __restrict__ z,
                          float* __restrict__ out, int Hin, int Hout){
    int o=blockIdx.x*blockDim.x+threadIdx.x;
    int total=NB*D*Hout*Hout;
    if(o>=total) return;
    int wo=o%Hout; int t=o/Hout;
    int ho=t%Hout; t/=Hout;       // t = n*D + c
    const float* xp = xin + (long)t*Hin*Hin;
    const float* zp = z   + (long)t*Hin*Hin;
    float mx=-INFINITY;
    #pragma unroll
    for(int kh=0;kh<3;kh++){
        int hh=2*ho-1+kh;
        if(hh<0||hh>=Hin) continue;
        #pragma unroll
        for(int kw=0;kw<3;kw++){
            int ww=2*wo-1+kw;
            if(ww<0||ww>=Hin) continue;
            float v=xp[hh*Hin+ww]+zp[hh*Hin+ww];
            mx=fmaxf(mx,v);
        }
    }
    out[o]=mx;
}

// ---------------- 7. global attention per (b, group) ----------------
// X[98][256] in smem; S=softmax(X X^T)*(1/16); out = S X
__global__ void k_gattn(){
    extern __shared__ float dsm[];
    float* X=dsm;              // 98*257
    float* S=dsm+98*257;       // 98*99
    int bg=blockIdx.x; int b=bg>>2, g=bg&3;
    int nx=g>>1, ny=g&1;
    int tid=threadIdx.x;
    for(int e=tid;e<NTOK*D;e+=256){
        int c=e&255, i=e>>8;
        int m=i/49, rr=i%49, w1=rr/7, w2=rr%7;
        int n=b*2+m;
        X[i*257+c]=g_xg2[(((long)n*D+c)*H3 + (nx*7+w1))*H3 + (ny*7+w2)];
    }
    __syncthreads();
    for(int p=tid;p<NTOK*NTOK;p+=256){
        int i=p/NTOK, j=p%NTOK;
        const float* xi=&X[i*257];
        const float* xj=&X[j*257];
        float a=0.f;
        #pragma unroll 8
        for(int k=0;k<D;k++) a+=xi[k]*xj[k];
        S[i*99+j]=a;
    }
    __syncthreads();
    int wd=tid>>5, lane=tid&31;
    for(int i=wd;i<NTOK;i+=8){
        float mx=-INFINITY;
        for(int j=lane;j<NTOK;j+=32) mx=fmaxf(mx,S[i*99+j]);
        for(int o=16;o>0;o>>=1) mx=fmaxf(mx,__shfl_xor_sync(0xffffffffu,mx,o));
        float sum=0.f;
        for(int j=lane;j<NTOK;j+=32){ float e2=expf(S[i*99+j]-mx); S[i*99+j]=e2; sum+=e2; }
        for(int o=16;o>0;o>>=1) sum+=__shfl_xor_sync(0xffffffffu,sum,o);
        float inv=0.0625f/sum;  // softmax * C^-0.5 (C=256)
        for(int j=lane;j<NTOK;j+=32) S[i*99+j]*=inv;
    }
    __syncthreads();
    for(int e=tid;e<NTOK*D;e+=256){
        int c=e&255, i=e>>8;
        float a=0.f;
        for(int j=0;j<NTOK;j++) a+=S[i*99+j]*X[j*257+c];
        g_gout[((long)bg*NTOK+i)*D+c]=a;
    }
}

// ---------------- 8. mean over 4 groups ----------------
__global__ void k_qmean(){
    int o=blockIdx.x*blockDim.x+threadIdx.x;
    if(o>=8*NTOK*D) return;
    int c=o&255; int t=o>>8; int i=t%NTOK; int b=t/NTOK;
    float a=0.f;
    for(int g=0;g<4;g++) a+=g_gout[(((long)(b*4+g)*NTOK)+i)*D+c];
    g_qglob[o]=a*0.25f;
}

// ---------------- 9. QKV GEMM (gathered A rows from x) ----------------
__global__ void k_gemm_qkv(const float* __restrict__ x, const float* __restrict__ Wm,
                           const float* __restrict__ bias){
    __shared__ float As[16][65];
    __shared__ float Bs[16][65];
    __shared__ long rowoff[64];
    int tid=threadIdx.x;
    int m0=blockIdx.y*64, n0=blockIdx.x*64;
    if(tid<64) rowoff[tid]=xrow_off(m0+tid);
    __syncthreads();
    float acc[4][4]={};
    int ty=tid>>4, tx=tid&15;
    for(int k0=0;k0<256;k0+=16){
        #pragma unroll
        for(int l=0;l<4;l++){
            int e=tid+l*256; int kk=e&15, mm=e>>4;
            As[kk][mm]=x[rowoff[mm]+k0+kk];
        }
        #pragma unroll
        for(int l=0;l<4;l++){
            int e=tid+l*256; int nn=e&63, kk=e>>6;
            Bs[kk][nn]=Wm[(k0+kk)*512 + n0+nn];
        }
        __syncthreads();
        #pragma unroll
        for(int kk=0;kk<16;kk++){
            float a[4],b[4];
            #pragma unroll
            for(int i=0;i<4;i++) a[i]=As[kk][ty*4+i];
            #pragma unroll
            for(int j=0;j<4;j++) b[j]=Bs[kk][tx*4+j];
            #pragma unroll
            for(int i=0;i<4;i++)
                #pragma unroll
                for(int j=0;j<4;j++) acc[i][j]+=a[i]*b[j];
        }
        __syncthreads();
    }
    #pragma unroll
    for(int i=0;i<4;i++){
        long r=m0+ty*4+i;
        #pragma unroll
        for(int j=0;j<4;j++){
            int n=n0+tx*4+j;
            g_kv[r*512+n]=acc[i][j]+bias[n];
        }
    }
}

// ---------------- 10. RPE bias gather ----------------
__global__ void k_bias(const float* __restrict__ rpe){
    int o=blockIdx.x*blockDim.x+threadIdx.x;
    if(o>=NH*NTOK*NTOK) return;
    int j=o%NTOK; int t=o/NTOK; int i=t%NTOK; int h=t/NTOK;
    int mi=i/49, ri=i%49, ai=ri/7, bi=ri%7;
    int mj=j/49, rj=j%49, aj=rj/7, bj=rj%7;
    int idx=(mi-mj+1)*169 + (ai-aj+6)*13 + (bi-bj+6);
    g_biasb[o]=rpe[idx*NH+h];
}

// ---------------- 11. window attention per (win, head) ----------------
__global__ void k_wattn(){
    extern __shared__ float dsm[];
    float* q=dsm;              // 98*33
    float* k=dsm+NTOK*33;
    float* v=dsm+2*NTOK*33;
    float* S=dsm+3*NTOK*33;    // 98*99
    int wh=blockIdx.x; int head=wh&7; int win=wh>>3;
    int b=win>>6;
    int tid=threadIdx.x;
    const float scale=0.17677669529663687f; // 32^-0.5
    for(int e=tid;e<NTOK*HD;e+=256){
        int i=e>>5, c=e&31;
        q[i*33+c]=g_qglob[((long)b*NTOK+i)*D + head*32+c]*scale;
        long kvb=((long)win*NTOK+i)*512 + head*32+c;
        k[i*33+c]=g_kv[kvb];
        v[i*33+c]=g_kv[kvb+256];
    }
    __syncthreads();
    const float* bs=&g_biasb[(long)head*NTOK*NTOK];
    for(int p=tid;p<NTOK*NTOK;p+=256){
        int i=p/NTOK, j=p%NTOK;
        float a=bs[p];
        const float* qi=&q[i*33];
        const float* kj=&k[j*33];
        #pragma unroll
        for(int c=0;c<HD;c++) a+=qi[c]*kj[c];
        S[i*99+j]=a;
    }
    __syncthreads();
    int wd=tid>>5, lane=tid&31;
    for(int i=wd;i<NTOK;i+=8){
        float mx=-INFINITY;
        for(int j=lane;j<NTOK;j+=32) mx=fmaxf(mx,S[i*99+j]);
        for(int o=16;o>0;o>>=1) mx=fmaxf(mx,__shfl_xor_sync(0xffffffffu,mx,o));
        float sum=0.f;
        for(int j=lane;j<NTOK;j+=32){ float e2=expf(S[i*99+j]-mx); S[i*99+j]=e2; sum+=e2; }
        for(int o=16;o>0;o>>=1) sum+=__shfl_xor_sync(0xffffffffu,sum,o);
        float inv=1.f/sum;
        for(int j=lane;j<NTOK;j+=32) S[i*99+j]*=inv;
    }
    __syncthreads();
    for(int e=tid;e<NTOK*HD;e+=256){
        int i=e>>5, c=e&31;
        float a=0.f;
        for(int j=0;j<NTOK;j++) a+=S[i*99+j]*v[j*33+c];
        g_aout[((long)win*NTOK+i)*D + head*32+c]=a;
    }
}

// ---------------- 12. to_out GEMM (scatter C rows to output layout) ----------------
__global__ void k_gemm_out(const float* __restrict__ Wm, float* __restrict__ outp){
    __shared__ float As[16][65];
    __shared__ float Bs[16][65];
    __shared__ long rowoff[64];
    int tid=threadIdx.x;
    int m0=blockIdx.y*64, n0=blockIdx.x*64;
    if(tid<64) rowoff[tid]=xrow_off(m0+tid);
    __syncthreads();
    float acc[4][4]={};
    int ty=tid>>4, tx=tid&15;
    for(int k0=0;k0<256;k0+=16){
        #pragma unroll
        for(int l=0;l<4;l++){
            int e=tid+l*256; int kk=e&15, mm=e>>4;
            As[kk][mm]=g_aout[(long)(m0+mm)*256 + k0+kk];
        }
        #pragma unroll
        for(int l=0;l<4;l++){
            int e=tid+l*256; int nn=e&63, kk=e>>6;
            Bs[kk][nn]=Wm[(k0+kk)*256 + n0+nn];
        }
        __syncthreads();
        #pragma unroll
        for(int kk=0;kk<16;kk++){
            float a[4],b[4];
            #pragma unroll
            for(int i=0;i<4;i++) a[i]=As[kk][ty*4+i];
            #pragma unroll
            for(int j=0;j<4;j++) b[j]=Bs[kk][tx*4+j];
            #pragma unroll
            for(int i=0;i<4;i++)
                #pragma unroll
                for(int j=0;j<4;j++) acc[i][j]+=a[i]*b[j];
        }
        __syncthreads();
    }
    #pragma unroll
    for(int i=0;i<4;i++){
        long ro=rowoff[ty*4+i];
        #pragma unroll
        for(int j=0;j<4;j++){
            int n=n0+tx*4+j;
            outp[ro+n]=acc[i][j];
        }
    }
}

// ---------------- host ----------------
extern "C" void kernel_launch(void* const* d_in, const int* in_sizes, int n_in,
                              void* d_out, int out_size){
    (void)in_sizes; (void)n_in; (void)out_size;
    const float* x       =(const float*)d_in[0];
    const float* qkv_w   =(const float*)d_in[1];
    const float* qkv_b   =(const float*)d_in[2];
    const float* to_out_w=(const float*)d_in[3];
    const float* rpe     =(const float*)d_in[4];
    const float* fe1_dw  =(const float*)d_in[5];
    const float* fe1_se1 =(const float*)d_in[6];
    const float* fe1_se2 =(const float*)d_in[7];
    const float* fe1_pw  =(const float*)d_in[8];
    const float* fe2_dw  =(const float*)d_in[9];
    const float* fe2_se1 =(const float*)d_in[10];
    const float* fe2_se2 =(const float*)d_in[11];
    const float* fe2_pw  =(const float*)d_in[12];
    float* outp=(float*)d_out;

    float *xg0,*yb,*zb,*xg1,*xg2,*smean,*svec;
    cudaGetSymbolAddress((void**)&xg0,  g_xg0);
    cudaGetSymbolAddress((void**)&yb,   g_y);
    cudaGetSymbolAddress((void**)&zb,   g_z);
    cudaGetSymbolAddress((void**)&xg1,  g_xg1);
    cudaGetSymbolAddress((void**)&xg2,  g_xg2);
    cudaGetSymbolAddress((void**)&smean,g_smean);
    cudaGetSymbolAddress((void**)&svec, g_svec);

    const int GATTN_SMEM=(98*257 + 98*99)*4;   // 139552 B
    const int WATTN_SMEM=(3*98*33 + 98*99)*4;  // 77616 B
    cudaFuncSetAttribute(k_gattn, cudaFuncAttributeMaxDynamicSharedMemorySize, GATTN_SMEM);
    cudaFuncSetAttribute(k_wattn, cudaFuncAttributeMaxDynamicSharedMemorySize, WATTN_SMEM);

    // rearrange
    k_rearrange<<<(NB*D*H1*H1+255)/256,256>>>(x);
    // FE1: 56 -> 28
    k_dwconv_gelu<<<(NB*D*H1*H1+255)/256,256>>>(xg0, fe1_dw, yb, H1);
    k_hwmean<<<NB*D,256>>>(yb, smean, H1);
    k_se<<<NB,256>>>(smean, fe1_se1, fe1_se2, svec);
    k_pwconv<<<dim3((H1*H1+63)/64,4,NB),256>>>(fe1_pw, yb, svec, zb, H1*H1);
    k_respool<<<(NB*D*H2*H2+255)/256,256>>>(xg0, zb, xg1, H1, H2);
    // FE2: 28 -> 14
    k_dwconv_gelu<<<(NB*D*H2*H2+255)/256,256>>>(xg1, fe2_dw, yb, H2);
    k_hwmean<<<NB*D,256>>>(yb, smean, H2);
    k_se<<<NB,256>>>(smean, fe2_se1, fe2_se2, svec);
    k_pwconv<<<dim3((H2*H2+63)/64,4,NB),256>>>(fe2_pw, yb, svec, zb, H2*H2);
    k_respool<<<(NB*D*H3*H3+255)/256,256>>>(xg1, zb, xg2, H2, H3);
    // global attention -> q_global
    k_gattn<<<32,256,GATTN_SMEM>>>();
    k_qmean<<<(8*NTOK*D+255)/256,256>>>();
    // window path
    k_gemm_qkv<<<dim3(8,MROWS/64),256>>>(x, qkv_w, qkv_b);
    k_bias<<<(NH*NTOK*NTOK+255)/256,256>>>(rpe);
    k_wattn<<<NWIN*NH,256,WATTN_SMEM>>>();
    k_gemm_out<<<dim3(4,MROWS/64),256>>>(to_out_w, outp);
}

// round 3
// speedup vs baseline: 1.3875x; 1.3875x over previous
#include <cuda_runtime.h>
#include <math.h>

#define NB   16
#define D    256
#define NH   8
#define NTOK 98
#define NWIN 512
#define SEH  64
#define H1   56
#define H2   28
#define H3   14
#define MROWS 50176

typedef unsigned long long ull;

// ---------------- scratch ----------------
__device__ __align__(16) float g_xg0[NB*D*H1*H1];
__device__ __align__(16) float g_y  [NB*D*H1*H1];
__device__ __align__(16) float g_z  [NB*D*H1*H1];
__device__ __align__(16) float g_xg1[NB*D*H2*H2];
__device__ __align__(16) float g_xg2[NB*D*H3*H3];
__device__ __align__(16) float g_smean[NB*D];
__device__ __align__(16) float g_svec [NB*D];
__device__ __align__(16) float g_gout [8*4*NTOK*D];
__device__ __align__(16) float g_qglob[8*NTOK*D];
__device__ __align__(16) float g_kv   [(size_t)MROWS*2*D];
__device__ __align__(16) float g_biasb[NH*NTOK*NTOK];
__device__ __align__(16) float g_aout [(size_t)MROWS*D];
__device__ __align__(16) float g_S    [32*NTOK*NTOK];

__device__ __forceinline__ float gelu_f(float v){
    return 0.5f*v*(1.0f+erff(v*0.70710678118654752440f));
}
__device__ __forceinline__ long xrow_off(int r){
    int win=r/NTOK, i=r%NTOK;
    int b=win>>6, gx=(win>>3)&7, gy=win&7;
    int m=i/49, rr=i%49, w1=rr/7, w2=rr%7;
    return (((((long)(b*2+m)*8+gx)*8+gy)*7+w1)*7+w2)*256;
}
__device__ __forceinline__ ull pk2(float a){ ull r; asm("mov.b64 %0,{%1,%1};":"=l"(r):"f"(a)); return r; }
__device__ __forceinline__ void fma2(ull&d, ull a, ull b){ asm("fma.rn.f32x2 %0,%1,%2,%0;":"+l"(d):"l"(a),"l"(b)); }
__device__ __forceinline__ float2 upk(ull v){ float2 r; asm("mov.b64 {%0,%1},%2;":"=f"(r.x),"=f"(r.y):"l"(v)); return r; }

// ---------------- rearrange ----------------
__global__ void k_rearrange(const float* __restrict__ x){
    int o=blockIdx.x*blockDim.x+threadIdx.x;
    if(o>=NB*D*H1*H1) return;
    int Wp=o%H1; int t=o/H1;
    int Hp=t%H1; t/=H1;
    int c=t%D;   int n=t/D;
    int b=n>>1, m=n&1;
    int gx=Hp/7, w1=Hp%7;
    int gy=Wp/7, w2=Wp%7;
    long off=(((((long)(b*2+m)*8+gx)*8+gy)*7+w1)*7+w2)*256 + c;
    g_xg0[o]=x[off];
}

// ---------------- depthwise 3x3 + gelu, 4 outputs/thread ----------------
__global__ void k_dwconv_gelu(const float* __restrict__ in, const float* __restrict__ dw,
                              float* __restrict__ out, int HW){
    int o=blockIdx.x*blockDim.x+threadIdx.x;
    int W4=HW>>2;
    int total=NB*D*HW*W4;
    if(o>=total) return;
    int wq=o%W4; int t=o/W4;
    int hy=t%HW; t/=HW;            // t = n*D + c
    int c=t&255;
    const float* ip=in+(long)t*HW*HW;
    const float* wp=dw+c*9;
    int wx0=wq*4;
    float acc[4]={0.f,0.f,0.f,0.f};
    #pragma unroll
    for(int kh=0;kh<3;kh++){
        int hh=hy+kh-1;
        if(hh<0||hh>=HW) continue;
        const float* rp=ip+hh*HW;
        float r[6];
        #pragma unroll
        for(int u=0;u<6;u++){
            int ww=wx0-1+u;
            r[u]=(ww>=0&&ww<HW)?rp[ww]:0.f;
        }
        #pragma unroll
        for(int kw=0;kw<3;kw++){
            float wv=wp[kh*3+kw];
            #pragma unroll
            for(int u=0;u<4;u++) acc[u]+=r[u+kw]*wv;
        }
    }
    float4 res;
    res.x=gelu_f(acc[0]); res.y=gelu_f(acc[1]); res.z=gelu_f(acc[2]); res.w=gelu_f(acc[3]);
    *(float4*)&out[(long)t*HW*HW + hy*HW + wx0]=res;
}

// ---------------- HW mean ----------------
__global__ void k_hwmean(const float* __restrict__ y, float* __restrict__ sm, int HW){
    int nc=blockIdx.x;
    const float* p=y+(long)nc*HW*HW;
    float s=0.f;
    for(int i=threadIdx.x;i<HW*HW;i+=blockDim.x) s+=p[i];
    __shared__ float red[256];
    red[threadIdx.x]=s; __syncthreads();
    for(int st=128;st>0;st>>=1){
        if(threadIdx.x<st) red[threadIdx.x]+=red[threadIdx.x+st];
        __syncthreads();
    }
    if(threadIdx.x==0) sm[nc]=red[0]/(float)(HW*HW);
}

// ---------------- SE MLP ----------------
__global__ void k_se(const float* __restrict__ sm, const float* __restrict__ se1,
                     const float* __restrict__ se2, float* __restrict__ sv){
    int n=blockIdx.x;
    __shared__ float sin_[D];
    __shared__ float hid[SEH];
    int t=threadIdx.x;
    sin_[t]=sm[n*D+t];
    __syncthreads();
    if(t<SEH){
        float a=0.f;
        for(int c=0;c<D;c++) a+=sin_[c]*se1[c*SEH+t];
        hid[t]=gelu_f(a);
    }
    __syncthreads();
    float a=0.f;
    for(int j=0;j<SEH;j++) a+=hid[j]*se2[j*D+t];
    sv[n*D+t]=1.f/(1.f+expf(-a));
}

// ---------------- unified GEMM: 128x128 tile, 8x8/thread, f32x2 ----------------
// mode 0: C=g_kv = gather(x) @ qkv_w + bias   (N=512)
// mode 1: C=scatter(out) = g_aout @ to_out_w  (N=256)
// mode 2: C=z[n] = (pw*sv[n]) @ y[n]          (N=P per image)
__global__ void __launch_bounds__(256,2) k_gemm(const float* __restrict__ Ab,
        const float* __restrict__ Bb, const float* __restrict__ aux,
        float* __restrict__ Cb, int mode, int ldb, int P){
    __shared__ float As[16][132];
    __shared__ float Bs[16][132];
    __shared__ long roff[128];
    __shared__ long ooff[128];
    __shared__ float bsh[128];
    int tid=threadIdx.x;
    int m0=blockIdx.y*128, n0=blockIdx.x*128;
    const float* Bp=Bb; float* Cp=Cb; const float* svp=aux;
    if(mode==2){
        long off=(long)blockIdx.z*256*P;
        Bp=Bb+off; Cp=Cb+off; svp=aux+blockIdx.z*256;
    }
    if(tid<128){
        if(mode==0){ roff[tid]=xrow_off(m0+tid); bsh[tid]=aux[n0+tid]; }
        else if(mode==1){ roff[tid]=(long)(m0+tid)*256; ooff[tid]=xrow_off(m0+tid); }
        else roff[tid]=(long)(m0+tid)*256;
    }
    __syncthreads();
    ull acc[8][4];
    #pragma unroll
    for(int i=0;i<8;i++)
        #pragma unroll
        for(int j=0;j<4;j++) acc[i][j]=0ull;
    int ty=tid>>4, tx=tid&15;
    for(int k0=0;k0<256;k0+=16){
        #pragma unroll
        for(int l=0;l<2;l++){
            int e=tid+l*256; int row=e>>2, kc=(e&3)*4;
            float4 a4=*(const float4*)&Ab[roff[row]+k0+kc];
            if(mode==2){
                float4 s4=*(const float4*)&svp[k0+kc];
                a4.x*=s4.x; a4.y*=s4.y; a4.z*=s4.z; a4.w*=s4.w;
            }
            As[kc+0][row]=a4.x; As[kc+1][row]=a4.y;
            As[kc+2][row]=a4.z; As[kc+3][row]=a4.w;
        }
        #pragma unroll
        for(int l=0;l<2;l++){
            int e=tid+l*256; int kk=e>>5, nn=(e&31)*4;
            int col=n0+nn;
            float4 b4;
            const float* brow=&Bp[(long)(k0+kk)*ldb];
            if(col+3<P) b4=*(const float4*)&brow[col];
            else{
                b4.x=(col  <P)?brow[col  ]:0.f;
                b4.y=(col+1<P)?brow[col+1]:0.f;
                b4.z=(col+2<P)?brow[col+2]:0.f;
                b4.w=(col+3<P)?brow[col+3]:0.f;
            }
            *(float4*)&Bs[kk][nn]=b4;
        }
        __syncthreads();
        #pragma unroll
        for(int kk=0;kk<16;kk++){
            float4 a0=*(const float4*)&As[kk][ty*8];
            float4 a1=*(const float4*)&As[kk][ty*8+4];
            const ull* bp=(const ull*)&Bs[kk][tx*8];
            ull b2[4]={bp[0],bp[1],bp[2],bp[3]};
            float av[8]={a0.x,a0.y,a0.z,a0.w,a1.x,a1.y,a1.z,a1.w};
            #pragma unroll
            for(int i=0;i<8;i++){
                ull a2=pk2(av[i]);
                #pragma unroll
                for(int j=0;j<4;j++) fma2(acc[i][j],a2,b2[j]);
            }
        }
        __syncthreads();
    }
    #pragma unroll
    for(int i=0;i<8;i++){
        int m=ty*8+i;
        float o[8];
        #pragma unroll
        for(int j=0;j<4;j++){ float2 t2=upk(acc[i][j]); o[2*j]=t2.x; o[2*j+1]=t2.y; }
        int n=n0+tx*8;
        if(mode==0){
            #pragma unroll
            for(int j=0;j<8;j++) o[j]+=bsh[tx*8+j];
            float4* dst=(float4*)&g_kv[(long)(m0+m)*512+n];
            dst[0]=make_float4(o[0],o[1],o[2],o[3]);
            dst[1]=make_float4(o[4],o[5],o[6],o[7]);
        }else if(mode==1){
            float4* dst=(float4*)&Cp[ooff[m]+n];
            dst[0]=make_float4(o[0],o[1],o[2],o[3]);
            dst[1]=make_float4(o[4],o[5],o[6],o[7]);
        }else{
            float* dst=&Cp[(long)(m0+m)*P+n];
            #pragma unroll
            for(int j=0;j<8;j++) if(n+j<P) dst[j]=o[j];
        }
    }
}

// ---------------- residual + maxpool ----------------
__global__ void k_respool(const float* __restrict__ xin, const float* __restrict__ z,
                          float* __restrict__ out, int Hin, int Hout){
    int o=blockIdx.x*blockDim.x+threadIdx.x;
    int total=NB*D*Hout*Hout;
    if(o>=total) return;
    int wo=o%Hout; int t=o/Hout;
    int ho=t%Hout; t/=Hout;
    const float* xp=xin+(long)t*Hin*Hin;
    const float* zp=z  +(long)t*Hin*Hin;
    float mx=-INFINITY;
    #pragma unroll
    for(int kh=0;kh<3;kh++){
        int hh=2*ho-1+kh;
        if(hh<0||hh>=Hin) continue;
        #pragma unroll
        for(int kw=0;kw<3;kw++){
            int ww=2*wo-1+kw;
            if(ww<0||ww>=Hin) continue;
            mx=fmaxf(mx,xp[hh*Hin+ww]+zp[hh*Hin+ww]);
        }
    }
    out[o]=mx;
}

// ---------------- gattn stage 1: S = softmax(X X^T)/16 ----------------
__global__ void k_gattn1(){
    extern __shared__ float dsm[];
    float* X=dsm;               // 98*260
    float* S=dsm+98*260;        // 26*100
    int bg=blockIdx.x, chunk=blockIdx.y;
    int b=bg>>2, g=bg&3, nx=g>>1, ny=g&1;
    int tid=threadIdx.x;
    for(int e=tid;e<98*256;e+=256){
        int c=e&255, i=e>>8;
        int m=i/49, rr=i%49, w1=rr/7, w2=rr%7;
        int n=b*2+m;
        X[i*260+c]=g_xg2[(((long)n*256+c)*14 + (nx*7+w1))*14 + (ny*7+w2)];
    }
    __syncthreads();
    int i0=chunk*26;
    int ni=min(26,98-i0);       // 26,26,26,20
    int npair=ni>>1;
    for(int t=tid;t<13*49;t+=256){
        int ip=t/49, jp=t%49;
        if(ip>=npair) continue;
        int i=i0+ip*2, j=jp*2;
        const ull* xi0=(const ull*)&X[i*260];
        const ull* xi1=(const ull*)&X[(i+1)*260];
        const ull* xj0=(const ull*)&X[j*260];
        const ull* xj1=(const ull*)&X[(j+1)*260];
        ull a00=0,a01=0,a10=0,a11=0;
        #pragma unroll 8
        for(int cp=0;cp<128;cp++){
            ull q0=xi0[cp],q1=xi1[cp],p0=xj0[cp],p1=xj1[cp];
            fma2(a00,q0,p0); fma2(a01,q0,p1); fma2(a10,q1,p0); fma2(a11,q1,p1);
        }
        float2 t00=upk(a00),t01=upk(a01),t10=upk(a10),t11=upk(a11);
        int il=i-i0;
        S[il*100+j]      =t00.x+t00.y;
        S[il*100+j+1]    =t01.x+t01.y;
        S[(il+1)*100+j]  =t10.x+t10.y;
        S[(il+1)*100+j+1]=t11.x+t11.y;
    }
    __syncthreads();
    int wd=tid>>5, lane=tid&31;
    for(int r=wd;r<ni;r+=8){
        float mx=-INFINITY;
        for(int j=lane;j<98;j+=32) mx=fmaxf(mx,S[r*100+j]);
        for(int o=16;o>0;o>>=1) mx=fmaxf(mx,__shfl_xor_sync(~0u,mx,o));
        float sum=0.f;
        for(int j=lane;j<98;j+=32){ float e=__expf(S[r*100+j]-mx); S[r*100+j]=e; sum+=e; }
        for(int o=16;o>0;o>>=1) sum+=__shfl_xor_sync(~0u,sum,o);
        float inv=0.0625f/sum;
        float* gs=&g_S[((long)bg*98 + i0+r)*98];
        for(int j=lane;j<98;j+=32) gs[j]=S[r*100+j]*inv;
    }
}

// ---------------- gattn stage 2: out = S X ----------------
__global__ void k_gattn2(){
    extern __shared__ float dsm[];
    float* X=dsm;               // 98*260
    float* Ssh=dsm+98*260;      // 26*100
    int bg=blockIdx.x, chunk=blockIdx.y;
    int b=bg>>2, g=bg&3, nx=g>>1, ny=g&1;
    int tid=threadIdx.x;
    for(int e=tid;e<98*256;e+=256){
        int c=e&255, i=e>>8;
        int m=i/49, rr=i%49, w1=rr/7, w2=rr%7;
        int n=b*2+m;
        X[i*260+c]=g_xg2[(((long)n*256+c)*14 + (nx*7+w1))*14 + (ny*7+w2)];
    }
    int i0=chunk*26;
    int ni=min(26,98-i0);
    for(int e=tid;e<ni*98;e+=256){
        int r=e/98, j=e%98;
        Ssh[r*100+j]=g_S[((long)bg*98 + i0+r)*98 + j];
    }
    __syncthreads();
    int npair=ni>>1;
    for(int t=tid;t<13*64;t+=256){
        int ip=t>>6, cq=t&63;
        if(ip>=npair) continue;
        int i=i0+2*ip, c=cq*4;
        ull a00=0,a01=0,a10=0,a11=0;
        const float* S0=&Ssh[(2*ip)*100];
        const float* S1=&Ssh[(2*ip+1)*100];
        for(int j=0;j<98;j++){
            ull s0=pk2(S0[j]), s1=pk2(S1[j]);
            const ull* vp=(const ull*)&X[j*260+c];
            ull v0=vp[0], v1=vp[1];
            fma2(a00,s0,v0); fma2(a01,s0,v1);
            fma2(a10,s1,v0); fma2(a11,s1,v1);
        }
        float2 x00=upk(a00),x01=upk(a01),x10=upk(a10),x11=upk(a11);
        long base=((long)bg*98+i)*256+c;
        *(float4*)&g_gout[base]    =make_float4(x00.x,x00.y,x01.x,x01.y);
        *(float4*)&g_gout[base+256]=make_float4(x10.x,x10.y,x11.x,x11.y);
    }
}

// ---------------- mean over 4 groups ----------------
__global__ void k_qmean(){
    int o=blockIdx.x*blockDim.x+threadIdx.x;
    if(o>=8*NTOK*D) return;
    int c=o&255; int t=o>>8; int i=t%NTOK; int b=t/NTOK;
    float a=0.f;
    for(int g=0;g<4;g++) a+=g_gout[(((long)(b*4+g)*NTOK)+i)*D+c];
    g_qglob[o]=a*0.25f;
}

// ---------------- RPE bias gather ----------------
__global__ void k_bias(const float* __restrict__ rpe){
    int o=blockIdx.x*blockDim.x+threadIdx.x;
    if(o>=NH*NTOK*NTOK) return;
    int j=o%NTOK; int t=o/NTOK; int i=t%NTOK; int h=t/NTOK;
    int mi=i/49, ri=i%49, ai=ri/7, bi=ri%7;
    int mj=j/49, rj=j%49, aj=rj/7, bj=rj%7;
    int idx=(mi-mj+1)*169 + (ai-aj+6)*13 + (bi-bj+6);
    g_biasb[o]=rpe[idx*NH+h];
}

// ---------------- window attention ----------------
__global__ void k_wattn(){
    extern __shared__ float dsm[];
    float* q=dsm;               // 98*36
    float* k=dsm+98*36;
    float* v=dsm+2*98*36;
    float* S=dsm+3*98*36;       // 98*100
    int wh=blockIdx.x; int head=wh&7; int win=wh>>3; int b=win>>6;
    int tid=threadIdx.x;
    const float scale=0.17677669529663687f;
    for(int e=tid;e<98*32;e+=256){
        int i=e>>5, c=e&31;
        q[i*36+c]=g_qglob[((long)b*98+i)*256 + head*32+c]*scale;
        long kvb=((long)win*98+i)*512 + head*32+c;
        k[i*36+c]=g_kv[kvb];
        v[i*36+c]=g_kv[kvb+256];
    }
    __syncthreads();
    const float* bs=&g_biasb[(long)head*98*98];
    for(int t=tid;t<49*49;t+=256){
        int ip=t/49, jp=t%49; int i=ip*2, j=jp*2;
        const ull* qi0=(const ull*)&q[i*36];
        const ull* qi1=(const ull*)&q[(i+1)*36];
        const ull* kj0=(const ull*)&k[j*36];
        const ull* kj1=(const ull*)&k[(j+1)*36];
        ull a00=0,a01=0,a10=0,a11=0;
        #pragma unroll
        for(int cp=0;cp<16;cp++){
            ull q0=qi0[cp],q1=qi1[cp],p0=kj0[cp],p1=kj1[cp];
            fma2(a00,q0,p0); fma2(a01,q0,p1); fma2(a10,q1,p0); fma2(a11,q1,p1);
        }
        float2 t00=upk(a00),t01=upk(a01),t10=upk(a10),t11=upk(a11);
        S[i*100+j]      =t00.x+t00.y+bs[i*98+j];
        S[i*100+j+1]    =t01.x+t01.y+bs[i*98+j+1];
        S[(i+1)*100+j]  =t10.x+t10.y+bs[(i+1)*98+j];
        S[(i+1)*100+j+1]=t11.x+t11.y+bs[(i+1)*98+j+1];
    }
    __syncthreads();
    int wd=tid>>5, lane=tid&31;
    for(int i=wd;i<98;i+=8){
        float mx=-INFINITY;
        for(int j=lane;j<98;j+=32) mx=fmaxf(mx,S[i*100+j]);
        for(int o=16;o>0;o>>=1) mx=fmaxf(mx,__shfl_xor_sync(~0u,mx,o));
        float sum=0.f;
        for(int j=lane;j<98;j+=32){ float e=__expf(S[i*100+j]-mx); S[i*100+j]=e; sum+=e; }
        for(int o=16;o>0;o>>=1) sum+=__shfl_xor_sync(~0u,sum,o);
        float inv=1.f/sum;
        for(int j=lane;j<98;j+=32) S[i*100+j]*=inv;
    }
    __syncthreads();
    for(int t=tid;t<49*8;t+=256){
        int ipair=t>>3, cq=t&7; int i=ipair*2, c=cq*4;
        ull a00=0,a01=0,a10=0,a11=0;
        const float* S0=&S[i*100];
        const float* S1=&S[(i+1)*100];
        for(int j=0;j<98;j++){
            ull s0=pk2(S0[j]), s1=pk2(S1[j]);
            const ull* vp=(const ull*)&v[j*36+c];
            ull v0=vp[0], v1=vp[1];
            fma2(a00,s0,v0); fma2(a01,s0,v1);
            fma2(a10,s1,v0); fma2(a11,s1,v1);
        }
        float2 x00=upk(a00),x01=upk(a01),x10=upk(a10),x11=upk(a11);
        long base=((long)win*98+i)*256 + head*32+c;
        *(float4*)&g_aout[base]    =make_float4(x00.x,x00.y,x01.x,x01.y);
        *(float4*)&g_aout[base+256]=make_float4(x10.x,x10.y,x11.x,x11.y);
    }
}

// ---------------- host ----------------
extern "C" void kernel_launch(void* const* d_in, const int* in_sizes, int n_in,
                              void* d_out, int out_size){
    (void)in_sizes; (void)n_in; (void)out_size;
    const float* x       =(const float*)d_in[0];
    const float* qkv_w   =(const float*)d_in[1];
    const float* qkv_b   =(const float*)d_in[2];
    const float* to_out_w=(const float*)d_in[3];
    const float* rpe     =(const float*)d_in[4];
    const float* fe1_dw  =(const float*)d_in[5];
    const float* fe1_se1 =(const float*)d_in[6];
    const float* fe1_se2 =(const float*)d_in[7];
    const float* fe1_pw  =(const float*)d_in[8];
    const float* fe2_dw  =(const float*)d_in[9];
    const float* fe2_se1 =(const float*)d_in[10];
    const float* fe2_se2 =(const float*)d_in[11];
    const float* fe2_pw  =(const float*)d_in[12];
    float* outp=(float*)d_out;

    float *xg0,*yb,*zb,*xg1,*xg2,*smean,*svec,*aout;
    cudaGetSymbolAddress((void**)&xg0,  g_xg0);
    cudaGetSymbolAddress((void**)&yb,   g_y);
    cudaGetSymbolAddress((void**)&zb,   g_z);
    cudaGetSymbolAddress((void**)&xg1,  g_xg1);
    cudaGetSymbolAddress((void**)&xg2,  g_xg2);
    cudaGetSymbolAddress((void**)&smean,g_smean);
    cudaGetSymbolAddress((void**)&svec, g_svec);
    cudaGetSymbolAddress((void**)&aout, g_aout);

    const int GATTN_SMEM=(98*260 + 26*100)*4;   // 112320
    const int WATTN_SMEM=(3*98*36 + 98*100)*4;  // 81536
    cudaFuncSetAttribute(k_gattn1, cudaFuncAttributeMaxDynamicSharedMemorySize, GATTN_SMEM);
    cudaFuncSetAttribute(k_gattn2, cudaFuncAttributeMaxDynamicSharedMemorySize, GATTN_SMEM);
    cudaFuncSetAttribute(k_wattn,  cudaFuncAttributeMaxDynamicSharedMemorySize, WATTN_SMEM);

    k_rearrange<<<(NB*D*H1*H1+255)/256,256>>>(x);
    // FE1: 56 -> 28
    k_dwconv_gelu<<<(NB*D*H1*H1/4+255)/256,256>>>(xg0, fe1_dw, yb, H1);
    k_hwmean<<<NB*D,256>>>(yb, smean, H1);
    k_se<<<NB,256>>>(smean, fe1_se1, fe1_se2, svec);
    k_gemm<<<dim3(25,2,NB),256>>>(fe1_pw, yb, svec, zb, 2, H1*H1, H1*H1);
    k_respool<<<(NB*D*H2*H2+255)/256,256>>>(xg0, zb, xg1, H1, H2);
    // FE2: 28 -> 14
    k_dwconv_gelu<<<(NB*D*H2*H2/4+255)/256,256>>>(xg1, fe2_dw, yb, H2);
    k_hwmean<<<NB*D,256>>>(yb, smean, H2);
    k_se<<<NB,256>>>(smean, fe2_se1, fe2_se2, svec);
    k_gemm<<<dim3(7,2,NB),256>>>(fe2_pw, yb, svec, zb, 2, H2*H2, H2*H2);
    k_respool<<<(NB*D*H3*H3+255)/256,256>>>(xg1, zb, xg2, H2, H3);
    // global attention
    k_gattn1<<<dim3(32,4),256,GATTN_SMEM>>>();
    k_gattn2<<<dim3(32,4),256,GATTN_SMEM>>>();
    k_qmean<<<(8*NTOK*D+255)/256,256>>>();
    // window path
    k_gemm<<<dim3(4,MROWS/128),256>>>(x, qkv_w, qkv_b, nullptr, 0, 512, 512);
    k_bias<<<(NH*NTOK*NTOK+255)/256,256>>>(rpe);
    k_wattn<<<NWIN*NH,256,WATTN_SMEM>>>();
    k_gemm<<<dim3(2,MROWS/128),256>>>(aout, to_out_w, nullptr, outp, 1, 256, 256);
}

// round 6
// speedup vs baseline: 1.6411x; 1.1828x over previous
#include <cuda_runtime.h>
#include <cuda_bf16.h>
#include <math.h>
#include <stdint.h>

#define NB   16
#define D    256
#define NH   8
#define NTOK 98
#define NWIN 512
#define SEH  64
#define H1   56
#define H2   28
#define H3   14
#define MROWS 50176

typedef unsigned long long ull;

// ---------------- scratch ----------------
__device__ __align__(16) float g_xg0[NB*D*H1*H1];
__device__ __align__(16) float g_y  [NB*D*H1*H1];
__device__ __align__(16) float g_z  [NB*D*H1*H1];
__device__ __align__(16) float g_xg1[NB*D*H2*H2];
__device__ __align__(16) float g_xg2[NB*D*H3*H3];
__device__ __align__(16) float g_smean[NB*D];
__device__ __align__(16) float g_svec [NB*D];
__device__ __align__(16) float g_gout [8*4*NTOK*D];
__device__ __align__(16) float g_qglob[8*NTOK*D];
__device__ __align__(16) float g_kv   [(size_t)MROWS*2*D];
__device__ __align__(16) float g_biasb[NH*NTOK*NTOK];
__device__ __align__(16) float g_aout [(size_t)MROWS*D];
__device__ __align__(16) float g_S    [32*NTOK*NTOK];
// transposed + hi/lo split weights: [N][K=256] bf16
__device__ __align__(16) __nv_bfloat16 g_Wqh[512*256], g_Wql[512*256];
__device__ __align__(16) __nv_bfloat16 g_Woh[256*256], g_Wol[256*256];

__device__ __forceinline__ float gelu_f(float v){
    return 0.5f*v*(1.0f+erff(v*0.70710678118654752440f));
}
__device__ __forceinline__ long xrow_off(int r){
    int win=r/NTOK, i=r%NTOK;
    int b=win>>6, gx=(win>>3)&7, gy=win&7;
    int m=i/49, rr=i%49, w1=rr/7, w2=rr%7;
    return (((((long)(b*2+m)*8+gx)*8+gy)*7+w1)*7+w2)*256;
}
__device__ __forceinline__ ull pk2(float a){ ull r; asm("mov.b64 %0,{%1,%1};":"=l"(r):"f"(a)); return r; }
__device__ __forceinline__ void fma2(ull&d, ull a, ull b){ asm("fma.rn.f32x2 %0,%1,%2,%0;":"+l"(d):"l"(a),"l"(b)); }
__device__ __forceinline__ float2 upk(ull v){ float2 r; asm("mov.b64 {%0,%1},%2;":"=f"(r.x),"=f"(r.y):"l"(v)); return r; }

__device__ __forceinline__ uint32_t smem_u32(const void* p){
    uint32_t a;
    asm("{ .reg .u64 t; cvta.to.shared.u64 t, %1; cvt.u32.u64 %0, t; }":"=r"(a):"l"(p));
    return a;
}
__device__ __forceinline__ void ldsm4(uint32_t* r, uint32_t a){
    asm volatile("ldmatrix.sync.aligned.m8n8.x4.shared.b16 {%0,%1,%2,%3},[%4];"
        :"=r"(r[0]),"=r"(r[1]),"=r"(r[2]),"=r"(r[3]):"r"(a));
}
__device__ __forceinline__ void ldsm2(uint32_t* r, uint32_t a){
    asm volatile("ldmatrix.sync.aligned.m8n8.x2.shared.b16 {%0,%1},[%2];"
        :"=r"(r[0]),"=r"(r[1]):"r"(a));
}
__device__ __forceinline__ void mma16816(float* d, const uint32_t* a, const uint32_t* b){
    asm volatile("mma.sync.aligned.m16n8k16.row.col.f32.bf16.bf16.f32 "
        "{%0,%1,%2,%3},{%4,%5,%6,%7},{%8,%9},{%0,%1,%2,%3};"
        : "+f"(d[0]),"+f"(d[1]),"+f"(d[2]),"+f"(d[3])
        : "r"(a[0]),"r"(a[1]),"r"(a[2]),"r"(a[3]),"r"(b[0]),"r"(b[1]));
}

// single extern shared symbol, one type everywhere
extern __shared__ float dsm[];

// ---------------- weight transpose + hi/lo split ----------------
__global__ void k_prep_w(const float* __restrict__ W, __nv_bfloat16* __restrict__ Wh,
                         __nv_bfloat16* __restrict__ Wl, int N){
    int o=blockIdx.x*blockDim.x+threadIdx.x;
    if(o>=N*256) return;
    int n=o>>8, k=o&255;
    float v=W[k*N+n];
    __nv_bfloat16 h=__float2bfloat16(v);
    Wh[o]=h;
    Wl[o]=__float2bfloat16(v-__bfloat162float(h));
}

// ---------------- HMMA GEMM: 128x128 tile, mma.sync bf16 hi/lo ----------------
// mode 0: A rows gathered from x (xrow_off), C = g_kv (+bias)
// mode 1: A rows linear from g_aout, C scattered to outp via xrow_off
#define SSTR 40   // smem row stride in halves (80B, conflict-free for ldmatrix)
__global__ void __launch_bounds__(256) k_mmagemm(const float* __restrict__ Asrc,
        const __nv_bfloat16* __restrict__ Wh, const __nv_bfloat16* __restrict__ Wl,
        const float* __restrict__ bias, float* __restrict__ Cb, int mode){
    __shared__ __align__(16) __nv_bfloat16 sAh[128*SSTR];
    __shared__ __align__(16) __nv_bfloat16 sAl[128*SSTR];
    __shared__ __align__(16) __nv_bfloat16 sBh[128*SSTR];
    __shared__ __align__(16) __nv_bfloat16 sBl[128*SSTR];
    __shared__ long rowoff[128];
    __shared__ long ooff[128];
    __shared__ float bsh[128];

    int tid=threadIdx.x;
    int wid=tid>>5, lane=tid&31;
    int wm=wid&1, wn=wid>>1;          // 2 warps in M x 4 warps in N
    int m0=blockIdx.y*128, n0=blockIdx.x*128;

    if(tid<128){
        if(mode==0){ rowoff[tid]=xrow_off(m0+tid); bsh[tid]=bias[n0+tid]; }
        else       { rowoff[tid]=(long)(m0+tid)*256; ooff[tid]=xrow_off(m0+tid); }
    }
    __syncthreads();

    uint32_t bAh=smem_u32(sAh), bAl=smem_u32(sAl);
    uint32_t bBh=smem_u32(sBh), bBl=smem_u32(sBl);

    float acc[4][4][4];
    #pragma unroll
    for(int i=0;i<4;i++)
        #pragma unroll
        for(int j=0;j<4;j++)
            #pragma unroll
            for(int e=0;e<4;e++) acc[i][j][e]=0.f;

    // per-thread ldmatrix address components
    int arow=lane&15,  acol=(lane>>4)*8;       // A: .x4
    int brow=lane&7,   bcol=((lane>>3)&1)*8;   // B: .x2

    int lrow=tid>>1, lcb=(tid&1)*16;           // smem fill: row + 16-col half

    for(int c=0;c<8;c++){
        int k0=c*32;
        // --- fill A (fp32 -> hi/lo bf16) ---
        {
            const float* src=&Asrc[rowoff[lrow]+k0+lcb];
            __nv_bfloat16 h[16], l[16];
            #pragma unroll
            for(int g=0;g<4;g++){
                float4 v=*(const float4*)&src[g*4];
                float vv[4]={v.x,v.y,v.z,v.w};
                #pragma unroll
                for(int u=0;u<4;u++){
                    __nv_bfloat16 hh=__float2bfloat16(vv[u]);
                    h[g*4+u]=hh;
                    l[g*4+u]=__float2bfloat16(vv[u]-__bfloat162float(hh));
                }
            }
            int sb=lrow*SSTR+lcb;
            *(uint4*)&sAh[sb]  =*(const uint4*)&h[0];
            *(uint4*)&sAh[sb+8]=*(const uint4*)&h[8];
            *(uint4*)&sAl[sb]  =*(const uint4*)&l[0];
            *(uint4*)&sAl[sb+8]=*(const uint4*)&l[8];
        }
        // --- fill B (already bf16 [n][256]) ---
        {
            const __nv_bfloat16* sh=&Wh[(long)(n0+lrow)*256+k0+lcb];
            const __nv_bfloat16* sl=&Wl[(long)(n0+lrow)*256+k0+lcb];
            int sb=lrow*SSTR+lcb;
            *(uint4*)&sBh[sb]  =*(const uint4*)&sh[0];
            *(uint4*)&sBh[sb+8]=*(const uint4*)&sh[8];
            *(uint4*)&sBl[sb]  =*(const uint4*)&sl[0];
            *(uint4*)&sBl[sb+8]=*(const uint4*)&sl[8];
        }
        __syncthreads();
        #pragma unroll
        for(int ks=0;ks<2;ks++){
            int kk=ks*16;
            uint32_t bh[4][2], bl[4][2];
            #pragma unroll
            for(int nt=0;nt<4;nt++){
                uint32_t boff=(uint32_t)((wn*32+nt*8+brow)*SSTR + kk+bcol)*2u;
                ldsm2(bh[nt], bBh+boff);
                ldsm2(bl[nt], bBl+boff);
            }
            #pragma unroll
            for(int mt=0;mt<4;mt++){
                uint32_t aoff=(uint32_t)((wm*64+mt*16+arow)*SSTR + kk+acol)*2u;
                uint32_t ah[4], al[4];
                ldsm4(ah, bAh+aoff);
                ldsm4(al, bAl+aoff);
                #pragma unroll
                for(int nt=0;nt<4;nt++){
                    mma16816(acc[mt][nt], ah, bh[nt]);
                    mma16816(acc[mt][nt], al, bh[nt]);
                    mma16816(acc[mt][nt], ah, bl[nt]);
                }
            }
        }
        __syncthreads();
    }

    // --- epilogue ---
    int rl=lane>>2, cl=(lane&3)*2;
    #pragma unroll
    for(int mt=0;mt<4;mt++){
        int r0=wm*64+mt*16+rl;       // local row (and +8)
        #pragma unroll
        for(int nt=0;nt<4;nt++){
            int nl=wn*32+nt*8+cl;    // local col
            float* d=acc[mt][nt];
            if(mode==0){
                float b0=bsh[nl], b1=bsh[nl+1];
                float* p0=&g_kv[(long)(m0+r0)*512 + n0+nl];
                float* p1=&g_kv[(long)(m0+r0+8)*512 + n0+nl];
                p0[0]=d[0]+b0; p0[1]=d[1]+b1;
                p1[0]=d[2]+b0; p1[1]=d[3]+b1;
            }else{
                float* p0=&Cb[ooff[r0]   + n0+nl];
                float* p1=&Cb[ooff[r0+8] + n0+nl];
                p0[0]=d[0]; p0[1]=d[1];
                p1[0]=d[2]; p1[1]=d[3];
            }
        }
    }
}

// ---------------- rearrange ----------------
__global__ void k_rearrange(const float* __restrict__ x){
    int o=blockIdx.x*blockDim.x+threadIdx.x;
    if(o>=NB*D*H1*H1) return;
    int Wp=o%H1; int t=o/H1;
    int Hp=t%H1; t/=H1;
    int c=t%D;   int n=t/D;
    int b=n>>1, m=n&1;
    int gx=Hp/7, w1=Hp%7;
    int gy=Wp/7, w2=Wp%7;
    long off=(((((long)(b*2+m)*8+gx)*8+gy)*7+w1)*7+w2)*256 + c;
    g_xg0[o]=x[off];
}

// ---------------- depthwise 3x3 + gelu ----------------
__global__ void k_dwconv_gelu(const float* __restrict__ in, const float* __restrict__ dw,
                              float* __restrict__ out, int HW){
    int o=blockIdx.x*blockDim.x+threadIdx.x;
    int W4=HW>>2;
    int total=NB*D*HW*W4;
    if(o>=total) return;
    int wq=o%W4; int t=o/W4;
    int hy=t%HW; t/=HW;
    int c=t&255;
    const float* ip=in+(long)t*HW*HW;
    const float* wp=dw+c*9;
    int wx0=wq*4;
    float acc[4]={0.f,0.f,0.f,0.f};
    #pragma unroll
    for(int kh=0;kh<3;kh++){
        int hh=hy+kh-1;
        if(hh<0||hh>=HW) continue;
        const float* rp=ip+hh*HW;
        float r[6];
        #pragma unroll
        for(int u=0;u<6;u++){
            int ww=wx0-1+u;
            r[u]=(ww>=0&&ww<HW)?rp[ww]:0.f;
        }
        #pragma unroll
        for(int kw=0;kw<3;kw++){
            float wv=wp[kh*3+kw];
            #pragma unroll
            for(int u=0;u<4;u++) acc[u]+=r[u+kw]*wv;
        }
    }
    float4 res;
    res.x=gelu_f(acc[0]); res.y=gelu_f(acc[1]); res.z=gelu_f(acc[2]); res.w=gelu_f(acc[3]);
    *(float4*)&out[(long)t*HW*HW + hy*HW + wx0]=res;
}

// ---------------- HW mean ----------------
__global__ void k_hwmean(const float* __restrict__ y, float* __restrict__ sm, int HW){
    int nc=blockIdx.x;
    const float* p=y+(long)nc*HW*HW;
    float s=0.f;
    for(int i=threadIdx.x;i<HW*HW;i+=blockDim.x) s+=p[i];
    __shared__ float red[256];
    red[threadIdx.x]=s; __syncthreads();
    for(int st=128;st>0;st>>=1){
        if(threadIdx.x<st) red[threadIdx.x]+=red[threadIdx.x+st];
        __syncthreads();
    }
    if(threadIdx.x==0) sm[nc]=red[0]/(float)(HW*HW);
}

// ---------------- SE MLP ----------------
__global__ void k_se(const float* __restrict__ sm, const float* __restrict__ se1,
                     const float* __restrict__ se2, float* __restrict__ sv){
    int n=blockIdx.x;
    __shared__ float sin_[D];
    __shared__ float hid[SEH];
    int t=threadIdx.x;
    sin_[t]=sm[n*D+t];
    __syncthreads();
    if(t<SEH){
        float a=0.f;
        for(int c=0;c<D;c++) a+=sin_[c]*se1[c*SEH+t];
        hid[t]=gelu_f(a);
    }
    __syncthreads();
    float a=0.f;
    for(int j=0;j<SEH;j++) a+=hid[j]*se2[j*D+t];
    sv[n*D+t]=1.f/(1.f+expf(-a));
}

// ---------------- fma2 GEMM (pwconv only) ----------------
__global__ void __launch_bounds__(256,2) k_gemm(const float* __restrict__ Ab,
        const float* __restrict__ Bb, const float* __restrict__ aux,
        float* __restrict__ Cb, int ldb, int P){
    __shared__ float As[16][132];
    __shared__ float Bs[16][132];
    int tid=threadIdx.x;
    int m0=blockIdx.y*128, n0=blockIdx.x*128;
    long off=(long)blockIdx.z*256*P;
    const float* Bp=Bb+off;
    float* Cp=Cb+off;
    const float* svp=aux+blockIdx.z*256;
    ull acc[8][4];
    #pragma unroll
    for(int i=0;i<8;i++)
        #pragma unroll
        for(int j=0;j<4;j++) acc[i][j]=0ull;
    int ty=tid>>4, tx=tid&15;
    for(int k0=0;k0<256;k0+=16){
        #pragma unroll
        for(int l=0;l<2;l++){
            int e=tid+l*256; int row=e>>2, kc=(e&3)*4;
            float4 a4=*(const float4*)&Ab[(long)(m0+row)*256+k0+kc];
            float4 s4=*(const float4*)&svp[k0+kc];
            a4.x*=s4.x; a4.y*=s4.y; a4.z*=s4.z; a4.w*=s4.w;
            As[kc+0][row]=a4.x; As[kc+1][row]=a4.y;
            As[kc+2][row]=a4.z; As[kc+3][row]=a4.w;
        }
        #pragma unroll
        for(int l=0;l<2;l++){
            int e=tid+l*256; int kk=e>>5, nn=(e&31)*4;
            int col=n0+nn;
            float4 b4;
            const float* brow=&Bp[(long)(k0+kk)*ldb];
            if(col+3<P) b4=*(const float4*)&brow[col];
            else{
                b4.x=(col  <P)?brow[col  ]:0.f;
                b4.y=(col+1<P)?brow[col+1]:0.f;
                b4.z=(col+2<P)?brow[col+2]:0.f;
                b4.w=(col+3<P)?brow[col+3]:0.f;
            }
            *(float4*)&Bs[kk][nn]=b4;
        }
        __syncthreads();
        #pragma unroll
        for(int kk=0;kk<16;kk++){
            float4 a0=*(const float4*)&As[kk][ty*8];
            float4 a1=*(const float4*)&As[kk][ty*8+4];
            const ull* bp=(const ull*)&Bs[kk][tx*8];
            ull b2[4]={bp[0],bp[1],bp[2],bp[3]};
            float av[8]={a0.x,a0.y,a0.z,a0.w,a1.x,a1.y,a1.z,a1.w};
            #pragma unroll
            for(int i=0;i<8;i++){
                ull a2=pk2(av[i]);
                #pragma unroll
                for(int j=0;j<4;j++) fma2(acc[i][j],a2,b2[j]);
            }
        }
        __syncthreads();
    }
    #pragma unroll
    for(int i=0;i<8;i++){
        int m=ty*8+i;
        float o[8];
        #pragma unroll
        for(int j=0;j<4;j++){ float2 t2=upk(acc[i][j]); o[2*j]=t2.x; o[2*j+1]=t2.y; }
        int n=n0+tx*8;
        float* dst=&Cp[(long)(m0+m)*P+n];
        #pragma unroll
        for(int j=0;j<8;j++) if(n+j<P) dst[j]=o[j];
    }
}

// ---------------- residual + maxpool ----------------
__global__ void k_respool(const float* __restrict__ xin, const float* __restrict__ z,
                          float* __restrict__ out, int Hin, int Hout){
    int o=blockIdx.x*blockDim.x+threadIdx.x;
    int total=NB*D*Hout*Hout;
    if(o>=total) return;
    int wo=o%Hout; int t=o/Hout;
    int ho=t%Hout; t/=Hout;
    const float* xp=xin+(long)t*Hin*Hin;
    const float* zp=z  +(long)t*Hin*Hin;
    float mx=-INFINITY;
    #pragma unroll
    for(int kh=0;kh<3;kh++){
        int hh=2*ho-1+kh;
        if(hh<0||hh>=Hin) continue;
        #pragma unroll
        for(int kw=0;kw<3;kw++){
            int ww=2*wo-1+kw;
            if(ww<0||ww>=Hin) continue;
            mx=fmaxf(mx,xp[hh*Hin+ww]+zp[hh*Hin+ww]);
        }
    }
    out[o]=mx;
}

// ---------------- gattn stage 1 ----------------
__global__ void k_gattn1(){
    float* X=dsm;
    float* S=dsm+98*260;
    int bg=blockIdx.x, chunk=blockIdx.y;
    int b=bg>>2, g=bg&3, nx=g>>1, ny=g&1;
    int tid=threadIdx.x;
    for(int e=tid;e<98*256;e+=256){
        int c=e&255, i=e>>8;
        int m=i/49, rr=i%49, w1=rr/7, w2=rr%7;
        int n=b*2+m;
        X[i*260+c]=g_xg2[(((long)n*256+c)*14 + (nx*7+w1))*14 + (ny*7+w2)];
    }
    __syncthreads();
    int i0=chunk*26;
    int ni=min(26,98-i0);
    int npair=ni>>1;
    for(int t=tid;t<13*49;t+=256){
        int ip=t/49, jp=t%49;
        if(ip>=npair) continue;
        int i=i0+ip*2, j=jp*2;
        const ull* xi0=(const ull*)&X[i*260];
        const ull* xi1=(const ull*)&X[(i+1)*260];
        const ull* xj0=(const ull*)&X[j*260];
        const ull* xj1=(const ull*)&X[(j+1)*260];
        ull a00=0,a01=0,a10=0,a11=0;
        #pragma unroll 8
        for(int cp=0;cp<128;cp++){
            ull q0=xi0[cp],q1=xi1[cp],p0=xj0[cp],p1=xj1[cp];
            fma2(a00,q0,p0); fma2(a01,q0,p1); fma2(a10,q1,p0); fma2(a11,q1,p1);
        }
        float2 t00=upk(a00),t01=upk(a01),t10=upk(a10),t11=upk(a11);
        int il=i-i0;
        S[il*100+j]      =t00.x+t00.y;
        S[il*100+j+1]    =t01.x+t01.y;
        S[(il+1)*100+j]  =t10.x+t10.y;
        S[(il+1)*100+j+1]=t11.x+t11.y;
    }
    __syncthreads();
    int wd=tid>>5, lane=tid&31;
    for(int r=wd;r<ni;r+=8){
        float mx=-INFINITY;
        for(int j=lane;j<98;j+=32) mx=fmaxf(mx,S[r*100+j]);
        for(int o=16;o>0;o>>=1) mx=fmaxf(mx,__shfl_xor_sync(~0u,mx,o));
        float sum=0.f;
        for(int j=lane;j<98;j+=32){ float e=__expf(S[r*100+j]-mx); S[r*100+j]=e; sum+=e; }
        for(int o=16;o>0;o>>=1) sum+=__shfl_xor_sync(~0u,sum,o);
        float inv=0.0625f/sum;
        float* gs=&g_S[((long)bg*98 + i0+r)*98];
        for(int j=lane;j<98;j+=32) gs[j]=S[r*100+j]*inv;
    }
}

// ---------------- gattn stage 2 ----------------
__global__ void k_gattn2(){
    float* X=dsm;
    float* Ssh=dsm+98*260;
    int bg=blockIdx.x, chunk=blockIdx.y;
    int b=bg>>2, g=bg&3, nx=g>>1, ny=g&1;
    int tid=threadIdx.x;
    for(int e=tid;e<98*256;e+=256){
        int c=e&255, i=e>>8;
        int m=i/49, rr=i%49, w1=rr/7, w2=rr%7;
        int n=b*2+m;
        X[i*260+c]=g_xg2[(((long)n*256+c)*14 + (nx*7+w1))*14 + (ny*7+w2)];
    }
    int i0=chunk*26;
    int ni=min(26,98-i0);
    for(int e=tid;e<ni*98;e+=256){
        int r=e/98, j=e%98;
        Ssh[r*100+j]=g_S[((long)bg*98 + i0+r)*98 + j];
    }
    __syncthreads();
    int npair=ni>>1;
    for(int t=tid;t<13*64;t+=256){
        int ip=t>>6, cq=t&63;
        if(ip>=npair) continue;
        int i=i0+2*ip, c=cq*4;
        ull a00=0,a01=0,a10=0,a11=0;
        const float* S0=&Ssh[(2*ip)*100];
        const float* S1=&Ssh[(2*ip+1)*100];
        for(int j=0;j<98;j++){
            ull s0=pk2(S0[j]), s1=pk2(S1[j]);
            const ull* vp=(const ull*)&X[j*260+c];
            ull v0=vp[0], v1=vp[1];
            fma2(a00,s0,v0); fma2(a01,s0,v1);
            fma2(a10,s1,v0); fma2(a11,s1,v1);
        }
        float2 x00=upk(a00),x01=upk(a01),x10=upk(a10),x11=upk(a11);
        long basep=((long)bg*98+i)*256+c;
        *(float4*)&g_gout[basep]    =make_float4(x00.x,x00.y,x01.x,x01.y);
        *(float4*)&g_gout[basep+256]=make_float4(x10.x,x10.y,x11.x,x11.y);
    }
}

// ---------------- mean over 4 groups ----------------
__global__ void k_qmean(){
    int o=blockIdx.x*blockDim.x+threadIdx.x;
    if(o>=8*NTOK*D) return;
    int c=o&255; int t=o>>8; int i=t%NTOK; int b=t/NTOK;
    float a=0.f;
    for(int g=0;g<4;g++) a+=g_gout[(((long)(b*4+g)*NTOK)+i)*D+c];
    g_qglob[o]=a*0.25f;
}

// ---------------- RPE bias gather ----------------
__global__ void k_bias(const float* __restrict__ rpe){
    int o=blockIdx.x*blockDim.x+threadIdx.x;
    if(o>=NH*NTOK*NTOK) return;
    int j=o%NTOK; int t=o/NTOK; int i=t%NTOK; int h=t/NTOK;
    int mi=i/49, ri=i%49, ai=ri/7, bi=ri%7;
    int mj=j/49, rj=j%49, aj=rj/7, bj=rj%7;
    int idx=(mi-mj+1)*169 + (ai-aj+6)*13 + (bi-bj+6);
    g_biasb[o]=rpe[idx*NH+h];
}

// ---------------- window attention ----------------
__global__ void k_wattn(){
    float* q=dsm;
    float* k=dsm+98*36;
    float* v=dsm+2*98*36;
    float* S=dsm+3*98*36;
    int wh=blockIdx.x; int head=wh&7; int win=wh>>3; int b=win>>6;
    int tid=threadIdx.x;
    const float scale=0.17677669529663687f;
    for(int e=tid;e<98*32;e+=256){
        int i=e>>5, c=e&31;
        q[i*36+c]=g_qglob[((long)b*98+i)*256 + head*32+c]*scale;
        long kvb=((long)win*98+i)*512 + head*32+c;
        k[i*36+c]=g_kv[kvb];
        v[i*36+c]=g_kv[kvb+256];
    }
    __syncthreads();
    const float* bs=&g_biasb[(long)head*98*98];
    for(int t=tid;t<49*49;t+=256){
        int ip=t/49, jp=t%49; int i=ip*2, j=jp*2;
        const ull* qi0=(const ull*)&q[i*36];
        const ull* qi1=(const ull*)&q[(i+1)*36];
        const ull* kj0=(const ull*)&k[j*36];
        const ull* kj1=(const ull*)&k[(j+1)*36];
        ull a00=0,a01=0,a10=0,a11=0;
        #pragma unroll
        for(int cp=0;cp<16;cp++){
            ull q0=qi0[cp],q1=qi1[cp],p0=kj0[cp],p1=kj1[cp];
            fma2(a00,q0,p0); fma2(a01,q0,p1); fma2(a10,q1,p0); fma2(a11,q1,p1);
        }
        float2 t00=upk(a00),t01=upk(a01),t10=upk(a10),t11=upk(a11);
        S[i*100+j]      =t00.x+t00.y+bs[i*98+j];
        S[i*100+j+1]    =t01.x+t01.y+bs[i*98+j+1];
        S[(i+1)*100+j]  =t10.x+t10.y+bs[(i+1)*98+j];
        S[(i+1)*100+j+1]=t11.x+t11.y+bs[(i+1)*98+j+1];
    }
    __syncthreads();
    int wd=tid>>5, lane=tid&31;
    for(int i=wd;i<98;i+=8){
        float mx=-INFINITY;
        for(int j=lane;j<98;j+=32) mx=fmaxf(mx,S[i*100+j]);
        for(int o=16;o>0;o>>=1) mx=fmaxf(mx,__shfl_xor_sync(~0u,mx,o));
        float sum=0.f;
        for(int j=lane;j<98;j+=32){ float e=__expf(S[i*100+j]-mx); S[i*100+j]=e; sum+=e; }
        for(int o=16;o>0;o>>=1) sum+=__shfl_xor_sync(~0u,sum,o);
        float inv=1.f/sum;
        for(int j=lane;j<98;j+=32) S[i*100+j]*=inv;
    }
    __syncthreads();
    for(int t=tid;t<49*8;t+=256){
        int ipair=t>>3, cq=t&7; int i=ipair*2, c=cq*4;
        ull a00=0,a01=0,a10=0,a11=0;
        const float* S0=&S[i*100];
        const float* S1=&S[(i+1)*100];
        for(int j=0;j<98;j++){
            ull s0=pk2(S0[j]), s1=pk2(S1[j]);
            const ull* vp=(const ull*)&v[j*36+c];
            ull v0=vp[0], v1=vp[1];
            fma2(a00,s0,v0); fma2(a01,s0,v1);
            fma2(a10,s1,v0); fma2(a11,s1,v1);
        }
        float2 x00=upk(a00),x01=upk(a01),x10=upk(a10),x11=upk(a11);
        long basep=((long)win*98+i)*256 + head*32+c;
        *(float4*)&g_aout[basep]    =make_float4(x00.x,x00.y,x01.x,x01.y);
        *(float4*)&g_aout[basep+256]=make_float4(x10.x,x10.y,x11.x,x11.y);
    }
}

// ---------------- host ----------------
extern "C" void kernel_launch(void* const* d_in, const int* in_sizes, int n_in,
                              void* d_out, int out_size){
    (void)in_sizes; (void)n_in; (void)out_size;
    const float* x       =(const float*)d_in[0];
    const float* qkv_w   =(const float*)d_in[1];
    const float* qkv_b   =(const float*)d_in[2];
    const float* to_out_w=(const float*)d_in[3];
    const float* rpe     =(const float*)d_in[4];
    const float* fe1_dw  =(const float*)d_in[5];
    const float* fe1_se1 =(const float*)d_in[6];
    const float* fe1_se2 =(const float*)d_in[7];
    const float* fe1_pw  =(const float*)d_in[8];
    const float* fe2_dw  =(const float*)d_in[9];
    const float* fe2_se1 =(const float*)d_in[10];
    const float* fe2_se2 =(const float*)d_in[11];
    const float* fe2_pw  =(const float*)d_in[12];
    float* outp=(float*)d_out;

    float *xg0,*yb,*zb,*xg1,*xg2,*smean,*svec,*aout;
    __nv_bfloat16 *wqh,*wql,*woh,*wol;
    cudaGetSymbolAddress((void**)&xg0,  g_xg0);
    cudaGetSymbolAddress((void**)&yb,   g_y);
    cudaGetSymbolAddress((void**)&zb,   g_z);
    cudaGetSymbolAddress((void**)&xg1,  g_xg1);
    cudaGetSymbolAddress((void**)&xg2,  g_xg2);
    cudaGetSymbolAddress((void**)&smean,g_smean);
    cudaGetSymbolAddress((void**)&svec, g_svec);
    cudaGetSymbolAddress((void**)&aout, g_aout);
    cudaGetSymbolAddress((void**)&wqh,  g_Wqh);
    cudaGetSymbolAddress((void**)&wql,  g_Wql);
    cudaGetSymbolAddress((void**)&woh,  g_Woh);
    cudaGetSymbolAddress((void**)&wol,  g_Wol);

    const int GATTN_SMEM=(98*260 + 26*100)*4;
    const int WATTN_SMEM=(3*98*36 + 98*100)*4;
    cudaFuncSetAttribute(k_gattn1, cudaFuncAttributeMaxDynamicSharedMemorySize, GATTN_SMEM);
    cudaFuncSetAttribute(k_gattn2, cudaFuncAttributeMaxDynamicSharedMemorySize, GATTN_SMEM);
    cudaFuncSetAttribute(k_wattn,  cudaFuncAttributeMaxDynamicSharedMemorySize, WATTN_SMEM);

    // weight prep (independent, run first)
    k_prep_w<<<(512*256+255)/256,256>>>(qkv_w, wqh, wql, 512);
    k_prep_w<<<(256*256+255)/256,256>>>(to_out_w, woh, wol, 256);

    k_rearrange<<<(NB*D*H1*H1+255)/256,256>>>(x);
    // FE1
    k_dwconv_gelu<<<(NB*D*H1*H1/4+255)/256,256>>>(xg0, fe1_dw, yb, H1);
    k_hwmean<<<NB*D,256>>>(yb, smean, H1);
    k_se<<<NB,256>>>(smean, fe1_se1, fe1_se2, svec);
    k_gemm<<<dim3(25,2,NB),256>>>(fe1_pw, yb, svec, zb, H1*H1, H1*H1);
    k_respool<<<(NB*D*H2*H2+255)/256,256>>>(xg0, zb, xg1, H1, H2);
    // FE2
    k_dwconv_gelu<<<(NB*D*H2*H2/4+255)/256,256>>>(xg1, fe2_dw, yb, H2);
    k_hwmean<<<NB*D,256>>>(yb, smean, H2);
    k_se<<<NB,256>>>(smean, fe2_se1, fe2_se2, svec);
    k_gemm<<<dim3(7,2,NB),256>>>(fe2_pw, yb, svec, zb, H2*H2, H2*H2);
    k_respool<<<(NB*D*H3*H3+255)/256,256>>>(xg1, zb, xg2, H2, H3);
    // global attention
    k_gattn1<<<dim3(32,4),256,GATTN_SMEM>>>();
    k_gattn2<<<dim3(32,4),256,GATTN_SMEM>>>();
    k_qmean<<<(8*NTOK*D+255)/256,256>>>();
    // window path (HMMA GEMMs)
    k_mmagemm<<<dim3(4,MROWS/128),256>>>(x, wqh, wql, qkv_b, nullptr, 0);
    k_bias<<<(NH*NTOK*NTOK+255)/256,256>>>(rpe);
    k_wattn<<<NWIN*NH,256,WATTN_SMEM>>>();
    k_mmagemm<<<dim3(2,MROWS/128),256>>>(aout, woh, wol, nullptr, outp, 1);
}

// round 7
// speedup vs baseline: 2.1929x; 1.3362x over previous
#include <cuda_runtime.h>
#include <cuda_bf16.h>
#include <math.h>
#include <stdint.h>

#define NB   16
#define D    256
#define NH   8
#define NTOK 98
#define NWIN 512
#define SEH  64
#define H1   56
#define H2   28
#define H3   14
#define MROWS 50176

typedef unsigned long long ull;

// ---------------- scratch ----------------
__device__ __align__(16) float g_xg0[NB*D*H1*H1];
__device__ __align__(16) float g_y  [NB*D*H1*H1];
__device__ __align__(16) float g_z  [NB*D*H1*H1];
__device__ __align__(16) float g_xg1[NB*D*H2*H2];
__device__ __align__(16) float g_xg2[NB*D*H3*H3];
__device__ __align__(16) float g_smean[NB*D];
__device__ __align__(16) float g_svec [NB*D];
__device__ __align__(16) float g_gout [8*4*NTOK*D];
__device__ __align__(16) float g_qglob[8*NTOK*D];
__device__ __align__(16) float g_kv   [(size_t)MROWS*2*D];
__device__ __align__(16) float g_biasb[NH*NTOK*NTOK];
__device__ __align__(16) float g_aout [(size_t)MROWS*D];
__device__ __align__(16) float g_S    [32*NTOK*NTOK];
__device__ __align__(16) __nv_bfloat16 g_Wqh[512*256], g_Wql[512*256];
__device__ __align__(16) __nv_bfloat16 g_Woh[256*256], g_Wol[256*256];

__device__ __forceinline__ float gelu_f(float v){
    return 0.5f*v*(1.0f+erff(v*0.70710678118654752440f));
}
__device__ __forceinline__ long xrow_off(int r){
    int win=r/NTOK, i=r%NTOK;
    int b=win>>6, gx=(win>>3)&7, gy=win&7;
    int m=i/49, rr=i%49, w1=rr/7, w2=rr%7;
    return (((((long)(b*2+m)*8+gx)*8+gy)*7+w1)*7+w2)*256;
}
__device__ __forceinline__ ull pk2(float a){ ull r; asm("mov.b64 %0,{%1,%1};":"=l"(r):"f"(a)); return r; }
__device__ __forceinline__ void fma2(ull&d, ull a, ull b){ asm("fma.rn.f32x2 %0,%1,%2,%0;":"+l"(d):"l"(a),"l"(b)); }
__device__ __forceinline__ float2 upk(ull v){ float2 r; asm("mov.b64 {%0,%1},%2;":"=f"(r.x),"=f"(r.y):"l"(v)); return r; }

__device__ __forceinline__ uint32_t smem_u32(const void* p){
    uint32_t a;
    asm("{ .reg .u64 t; cvta.to.shared.u64 t, %1; cvt.u32.u64 %0, t; }":"=r"(a):"l"(p));
    return a;
}
__device__ __forceinline__ void ldsm4(uint32_t* r, uint32_t a){
    asm volatile("ldmatrix.sync.aligned.m8n8.x4.shared.b16 {%0,%1,%2,%3},[%4];"
        :"=r"(r[0]),"=r"(r[1]),"=r"(r[2]),"=r"(r[3]):"r"(a));
}
__device__ __forceinline__ void ldsm2(uint32_t* r, uint32_t a){
    asm volatile("ldmatrix.sync.aligned.m8n8.x2.shared.b16 {%0,%1},[%2];"
        :"=r"(r[0]),"=r"(r[1]):"r"(a));
}
__device__ __forceinline__ void mma16816(float* d, const uint32_t* a, const uint32_t* b){
    asm volatile("mma.sync.aligned.m16n8k16.row.col.f32.bf16.bf16.f32 "
        "{%0,%1,%2,%3},{%4,%5,%6,%7},{%8,%9},{%0,%1,%2,%3};"
        : "+f"(d[0]),"+f"(d[1]),"+f"(d[2]),"+f"(d[3])
        : "r"(a[0]),"r"(a[1]),"r"(a[2]),"r"(a[3]),"r"(b[0]),"r"(b[1]));
}
__device__ __forceinline__ uint32_t bsplit2(float a, float b, uint32_t& lo){
    __nv_bfloat16 ha=__float2bfloat16(a), hb=__float2bfloat16(b);
    __nv_bfloat16 la=__float2bfloat16(a-__bfloat162float(ha));
    __nv_bfloat16 lb=__float2bfloat16(b-__bfloat162float(hb));
    __nv_bfloat162 h2; h2.x=ha; h2.y=hb;
    __nv_bfloat162 l2; l2.x=la; l2.y=lb;
    lo=*(uint32_t*)&l2;
    return *(uint32_t*)&h2;
}

extern __shared__ float dsm[];

// ---------------- weight transpose + hi/lo split ----------------
__global__ void k_prep_w(const float* __restrict__ W, __nv_bfloat16* __restrict__ Wh,
                         __nv_bfloat16* __restrict__ Wl, int N){
    int o=blockIdx.x*blockDim.x+threadIdx.x;
    if(o>=N*256) return;
    int n=o>>8, k=o&255;
    float v=W[k*N+n];
    __nv_bfloat16 h=__float2bfloat16(v);
    Wh[o]=h;
    Wl[o]=__float2bfloat16(v-__bfloat162float(h));
}

// ---------------- HMMA GEMM (QKV / to_out) ----------------
#define SSTR 40
__global__ void __launch_bounds__(256) k_mmagemm(const float* __restrict__ Asrc,
        const __nv_bfloat16* __restrict__ Wh, const __nv_bfloat16* __restrict__ Wl,
        const float* __restrict__ bias, float* __restrict__ Cb, int mode){
    __shared__ __align__(16) __nv_bfloat16 sAh[128*SSTR];
    __shared__ __align__(16) __nv_bfloat16 sAl[128*SSTR];
    __shared__ __align__(16) __nv_bfloat16 sBh[128*SSTR];
    __shared__ __align__(16) __nv_bfloat16 sBl[128*SSTR];
    __shared__ long rowoff[128];
    __shared__ long ooff[128];
    __shared__ float bsh[128];

    int tid=threadIdx.x;
    int wid=tid>>5, lane=tid&31;
    int wm=wid&1, wn=wid>>1;
    int m0=blockIdx.y*128, n0=blockIdx.x*128;

    if(tid<128){
        if(mode==0){ rowoff[tid]=xrow_off(m0+tid); bsh[tid]=bias[n0+tid]; }
        else       { rowoff[tid]=(long)(m0+tid)*256; ooff[tid]=xrow_off(m0+tid); }
    }
    __syncthreads();

    uint32_t bAh=smem_u32(sAh), bAl=smem_u32(sAl);
    uint32_t bBh=smem_u32(sBh), bBl=smem_u32(sBl);

    float acc[4][4][4];
    #pragma unroll
    for(int i=0;i<4;i++)
        #pragma unroll
        for(int j=0;j<4;j++)
            #pragma unroll
            for(int e=0;e<4;e++) acc[i][j][e]=0.f;

    int arow=lane&15,  acol=(lane>>4)*8;
    int brow=lane&7,   bcol=((lane>>3)&1)*8;
    int lrow=tid>>1, lcb=(tid&1)*16;

    for(int c=0;c<8;c++){
        int k0=c*32;
        {
            const float* src=&Asrc[rowoff[lrow]+k0+lcb];
            __nv_bfloat16 h[16], l[16];
            #pragma unroll
            for(int g=0;g<4;g++){
                float4 v=*(const float4*)&src[g*4];
                float vv[4]={v.x,v.y,v.z,v.w};
                #pragma unroll
                for(int u=0;u<4;u++){
                    __nv_bfloat16 hh=__float2bfloat16(vv[u]);
                    h[g*4+u]=hh;
                    l[g*4+u]=__float2bfloat16(vv[u]-__bfloat162float(hh));
                }
            }
            int sb=lrow*SSTR+lcb;
            *(uint4*)&sAh[sb]  =*(const uint4*)&h[0];
            *(uint4*)&sAh[sb+8]=*(const uint4*)&h[8];
            *(uint4*)&sAl[sb]  =*(const uint4*)&l[0];
            *(uint4*)&sAl[sb+8]=*(const uint4*)&l[8];
        }
        {
            const __nv_bfloat16* sh=&Wh[(long)(n0+lrow)*256+k0+lcb];
            const __nv_bfloat16* sl=&Wl[(long)(n0+lrow)*256+k0+lcb];
            int sb=lrow*SSTR+lcb;
            *(uint4*)&sBh[sb]  =*(const uint4*)&sh[0];
            *(uint4*)&sBh[sb+8]=*(const uint4*)&sh[8];
            *(uint4*)&sBl[sb]  =*(const uint4*)&sl[0];
            *(uint4*)&sBl[sb+8]=*(const uint4*)&sl[8];
        }
        __syncthreads();
        #pragma unroll
        for(int ks=0;ks<2;ks++){
            int kk=ks*16;
            uint32_t bh[4][2], bl[4][2];
            #pragma unroll
            for(int nt=0;nt<4;nt++){
                uint32_t boff=(uint32_t)((wn*32+nt*8+brow)*SSTR + kk+bcol)*2u;
                ldsm2(bh[nt], bBh+boff);
                ldsm2(bl[nt], bBl+boff);
            }
            #pragma unroll
            for(int mt=0;mt<4;mt++){
                uint32_t aoff=(uint32_t)((wm*64+mt*16+arow)*SSTR + kk+acol)*2u;
                uint32_t ah[4], al[4];
                ldsm4(ah, bAh+aoff);
                ldsm4(al, bAl+aoff);
                #pragma unroll
                for(int nt=0;nt<4;nt++){
                    mma16816(acc[mt][nt], ah, bh[nt]);
                    mma16816(acc[mt][nt], al, bh[nt]);
                    mma16816(acc[mt][nt], ah, bl[nt]);
                }
            }
        }
        __syncthreads();
    }

    int rl=lane>>2, cl=(lane&3)*2;
    #pragma unroll
    for(int mt=0;mt<4;mt++){
        int r0=wm*64+mt*16+rl;
        #pragma unroll
        for(int nt=0;nt<4;nt++){
            int nl=wn*32+nt*8+cl;
            float* d=acc[mt][nt];
            if(mode==0){
                float b0=bsh[nl], b1=bsh[nl+1];
                float* p0=&g_kv[(long)(m0+r0)*512 + n0+nl];
                float* p1=&g_kv[(long)(m0+r0+8)*512 + n0+nl];
                p0[0]=d[0]+b0; p0[1]=d[1]+b1;
                p1[0]=d[2]+b0; p1[1]=d[3]+b1;
            }else{
                float* p0=&Cb[ooff[r0]   + n0+nl];
                float* p1=&Cb[ooff[r0+8] + n0+nl];
                p0[0]=d[0]; p0[1]=d[1];
                p1[0]=d[2]; p1[1]=d[3];
            }
        }
    }
}

// ---------------- HMMA window attention ----------------
// per (win, head) block: S=QK^T*scale+bias -> softmax -> out=P V, all hi/lo bf16 HMMA
#define QSTR 40      // q/k smem stride (halves)
#define PSTR 120     // p / vT stride (halves)
// smem half-offsets
#define OQH 0
#define OQL (OQH+112*QSTR)
#define OKH (OQL+112*QSTR)
#define OKL (OKH+112*QSTR)
#define OVH (OKL+112*QSTR)
#define OVL (OVH+32*PSTR)
#define OPH (OVL+32*PSTR)
#define OPL (OPH+112*PSTR)
#define WSM_HALVES (OPL+112*PSTR)   // 17920 + 7680 + 26880 = 52480 halves
__global__ void __launch_bounds__(256) k_wattn(){
    __nv_bfloat16* sb=(__nv_bfloat16*)dsm;
    int wh=blockIdx.x; int head=wh&7; int win=wh>>3; int b=win>>6;
    int tid=threadIdx.x, wid=tid>>5, lane=tid&31;
    const float scale=0.17677669529663687f;

    // zero whole buffer (covers all pads)
    for(int e=tid;e<WSM_HALVES/8;e+=256) ((uint4*)sb)[e]=make_uint4(0,0,0,0);
    __syncthreads();

    // load q,k (rows<98), hi/lo split
    for(int e=tid;e<224;e+=256){
        int row=e>>1, half=(e&1)*16;
        if(row<98){
            const float* qs=&g_qglob[((long)b*98+row)*256 + head*32 + half];
            const float* ks=&g_kv[(((long)win*98+row))*512 + head*32 + half];
            uint32_t qh[8], ql[8], kh[8], kl[8];
            #pragma unroll
            for(int u=0;u<8;u++){
                float q0=qs[2*u]*scale, q1=qs[2*u+1]*scale;
                qh[u]=bsplit2(q0,q1,ql[u]);
                kh[u]=bsplit2(ks[2*u],ks[2*u+1],kl[u]);
            }
            int sbo=row*QSTR+half;
            *(uint4*)&sb[OQH+sbo]  =*(uint4*)&qh[0];
            *(uint4*)&sb[OQH+sbo+8]=*(uint4*)&qh[4];
            *(uint4*)&sb[OQL+sbo]  =*(uint4*)&ql[0];
            *(uint4*)&sb[OQL+sbo+8]=*(uint4*)&ql[4];
            *(uint4*)&sb[OKH+sbo]  =*(uint4*)&kh[0];
            *(uint4*)&sb[OKH+sbo+8]=*(uint4*)&kh[4];
            *(uint4*)&sb[OKL+sbo]  =*(uint4*)&kl[0];
            *(uint4*)&sb[OKL+sbo+8]=*(uint4*)&kl[4];
        }
    }
    // load v transposed: vT[c][j]
    for(int e=tid;e<196;e+=256){
        int row=e>>1, half=(e&1)*16;
        const float* vs=&g_kv[(((long)win*98+row))*512 + 256 + head*32 + half];
        #pragma unroll
        for(int u=0;u<16;u++){
            float vv=vs[u];
            __nv_bfloat16 h=__float2bfloat16(vv);
            __nv_bfloat16 l=__float2bfloat16(vv-__bfloat162float(h));
            int c=half+u;
            sb[OVH+c*PSTR+row]=h;
            sb[OVL+c*PSTR+row]=l;
        }
    }
    __syncthreads();

    uint32_t base=smem_u32(sb);
    int arow=lane&15, acol=(lane>>4)*8;
    int brow=lane&7,  bcol=((lane>>3)&1)*8;
    int rl=lane>>2, cl=(lane&3)*2;

    if(wid<7){
        // ---- phase 1: S = QK^T (+bias), softmax, store P hi/lo ----
        float sacc[13][4];
        #pragma unroll
        for(int nt=0;nt<13;nt++){
            #pragma unroll
            for(int e2=0;e2<4;e2++) sacc[nt][e2]=0.f;
        }
        #pragma unroll
        for(int kc=0;kc<2;kc++){
            int kk=kc*16;
            uint32_t aoff=(uint32_t)((wid*16+arow)*QSTR + kk+acol)*2u;
            uint32_t ah[4], al[4];
            ldsm4(ah, base+(OQH*2u)+aoff);
            ldsm4(al, base+(OQL*2u)+aoff);
            #pragma unroll
            for(int nt=0;nt<13;nt++){
                uint32_t boff=(uint32_t)((nt*8+brow)*QSTR + kk+bcol)*2u;
                uint32_t bh[2], bl[2];
                ldsm2(bh, base+(OKH*2u)+boff);
                ldsm2(bl, base+(OKL*2u)+boff);
                mma16816(sacc[nt], ah, bh);
                mma16816(sacc[nt], al, bh);
                mma16816(sacc[nt], ah, bl);
            }
        }
        // bias + mask
        int r0=wid*16+rl, r1=r0+8;
        const float* bbase=&g_biasb[(long)head*9604];
        #pragma unroll
        for(int nt=0;nt<13;nt++){
            int j0=nt*8+cl;
            if(j0>=98){
                sacc[nt][0]=-1e30f; sacc[nt][1]=-1e30f;
                sacc[nt][2]=-1e30f; sacc[nt][3]=-1e30f;
            }else{
                if(r0<98){
                    float2 bb=*(const float2*)&bbase[r0*98+j0];
                    sacc[nt][0]+=bb.x; sacc[nt][1]+=bb.y;
                }
                if(r1<98){
                    float2 bb=*(const float2*)&bbase[r1*98+j0];
                    sacc[nt][2]+=bb.x; sacc[nt][3]+=bb.y;
                }
            }
        }
        // softmax rows r0, r1 (4-lane groups share a row)
        float mx0=-1e30f, mx1=-1e30f;
        #pragma unroll
        for(int nt=0;nt<13;nt++){
            mx0=fmaxf(mx0,fmaxf(sacc[nt][0],sacc[nt][1]));
            mx1=fmaxf(mx1,fmaxf(sacc[nt][2],sacc[nt][3]));
        }
        mx0=fmaxf(mx0,__shfl_xor_sync(~0u,mx0,1)); mx0=fmaxf(mx0,__shfl_xor_sync(~0u,mx0,2));
        mx1=fmaxf(mx1,__shfl_xor_sync(~0u,mx1,1)); mx1=fmaxf(mx1,__shfl_xor_sync(~0u,mx1,2));
        float sum0=0.f, sum1=0.f;
        #pragma unroll
        for(int nt=0;nt<13;nt++){
            sacc[nt][0]=__expf(sacc[nt][0]-mx0); sum0+=sacc[nt][0];
            sacc[nt][1]=__expf(sacc[nt][1]-mx0); sum0+=sacc[nt][1];
            sacc[nt][2]=__expf(sacc[nt][2]-mx1); sum1+=sacc[nt][2];
            sacc[nt][3]=__expf(sacc[nt][3]-mx1); sum1+=sacc[nt][3];
        }
        sum0+=__shfl_xor_sync(~0u,sum0,1); sum0+=__shfl_xor_sync(~0u,sum0,2);
        sum1+=__shfl_xor_sync(~0u,sum1,1); sum1+=__shfl_xor_sync(~0u,sum1,2);
        float inv0=1.f/sum0, inv1=1.f/sum1;
        // store P hi/lo
        #pragma unroll
        for(int nt=0;nt<13;nt++){
            int j0=nt*8+cl;
            uint32_t lo0, lo1;
            uint32_t hi0=bsplit2(sacc[nt][0]*inv0, sacc[nt][1]*inv0, lo0);
            uint32_t hi1=bsplit2(sacc[nt][2]*inv1, sacc[nt][3]*inv1, lo1);
            *(uint32_t*)&sb[OPH+r0*PSTR+j0]=hi0;
            *(uint32_t*)&sb[OPL+r0*PSTR+j0]=lo0;
            *(uint32_t*)&sb[OPH+r1*PSTR+j0]=hi1;
            *(uint32_t*)&sb[OPL+r1*PSTR+j0]=lo1;
        }
    }
    __syncthreads();
    if(wid<7){
        // ---- phase 2: out = P V ----
        float oacc[4][4];
        #pragma unroll
        for(int nt=0;nt<4;nt++)
            #pragma unroll
            for(int e2=0;e2<4;e2++) oacc[nt][e2]=0.f;
        #pragma unroll
        for(int kc=0;kc<7;kc++){
            int kk=kc*16;
            uint32_t aoff=(uint32_t)((wid*16+arow)*PSTR + kk+acol)*2u;
            uint32_t ah[4], al[4];
            ldsm4(ah, base+(OPH*2u)+aoff);
            ldsm4(al, base+(OPL*2u)+aoff);
            #pragma unroll
            for(int nt=0;nt<4;nt++){
                uint32_t boff=(uint32_t)((nt*8+brow)*PSTR + kk+bcol)*2u;
                uint32_t bh[2], bl[2];
                ldsm2(bh, base+(OVH*2u)+boff);
                ldsm2(bl, base+(OVL*2u)+boff);
                mma16816(oacc[nt], ah, bh);
                mma16816(oacc[nt], al, bh);
                mma16816(oacc[nt], ah, bl);
            }
        }
        int r0=wid*16+rl, r1=r0+8;
        #pragma unroll
        for(int nt=0;nt<4;nt++){
            int c=nt*8+cl;
            if(r0<98)
                *(float2*)&g_aout[((long)win*98+r0)*256 + head*32 + c]=make_float2(oacc[nt][0],oacc[nt][1]);
            if(r1<98)
                *(float2*)&g_aout[((long)win*98+r1)*256 + head*32 + c]=make_float2(oacc[nt][2],oacc[nt][3]);
        }
    }
}

// ---------------- rearrange ----------------
__global__ void k_rearrange(const float* __restrict__ x){
    int o=blockIdx.x*blockDim.x+threadIdx.x;
    if(o>=NB*D*H1*H1) return;
    int Wp=o%H1; int t=o/H1;
    int Hp=t%H1; t/=H1;
    int c=t%D;   int n=t/D;
    int b=n>>1, m=n&1;
    int gx=Hp/7, w1=Hp%7;
    int gy=Wp/7, w2=Wp%7;
    long off=(((((long)(b*2+m)*8+gx)*8+gy)*7+w1)*7+w2)*256 + c;
    g_xg0[o]=x[off];
}

// ---------------- depthwise 3x3 + gelu ----------------
__global__ void k_dwconv_gelu(const float* __restrict__ in, const float* __restrict__ dw,
                              float* __restrict__ out, int HW){
    int o=blockIdx.x*blockDim.x+threadIdx.x;
    int W4=HW>>2;
    int total=NB*D*HW*W4;
    if(o>=total) return;
    int wq=o%W4; int t=o/W4;
    int hy=t%HW; t/=HW;
    int c=t&255;
    const float* ip=in+(long)t*HW*HW;
    const float* wp=dw+c*9;
    int wx0=wq*4;
    float acc[4]={0.f,0.f,0.f,0.f};
    #pragma unroll
    for(int kh=0;kh<3;kh++){
        int hh=hy+kh-1;
        if(hh<0||hh>=HW) continue;
        const float* rp=ip+hh*HW;
        float r[6];
        #pragma unroll
        for(int u=0;u<6;u++){
            int ww=wx0-1+u;
            r[u]=(ww>=0&&ww<HW)?rp[ww]:0.f;
        }
        #pragma unroll
        for(int kw=0;kw<3;kw++){
            float wv=wp[kh*3+kw];
            #pragma unroll
            for(int u=0;u<4;u++) acc[u]+=r[u+kw]*wv;
        }
    }
    float4 res;
    res.x=gelu_f(acc[0]); res.y=gelu_f(acc[1]); res.z=gelu_f(acc[2]); res.w=gelu_f(acc[3]);
    *(float4*)&out[(long)t*HW*HW + hy*HW + wx0]=res;
}

// ---------------- HW mean ----------------
__global__ void k_hwmean(const float* __restrict__ y, float* __restrict__ sm, int HW){
    int nc=blockIdx.x;
    const float* p=y+(long)nc*HW*HW;
    float s=0.f;
    for(int i=threadIdx.x;i<HW*HW;i+=blockDim.x) s+=p[i];
    __shared__ float red[256];
    red[threadIdx.x]=s; __syncthreads();
    for(int st=128;st>0;st>>=1){
        if(threadIdx.x<st) red[threadIdx.x]+=red[threadIdx.x+st];
        __syncthreads();
    }
    if(threadIdx.x==0) sm[nc]=red[0]/(float)(HW*HW);
}

// ---------------- SE MLP ----------------
__global__ void k_se(const float* __restrict__ sm, const float* __restrict__ se1,
                     const float* __restrict__ se2, float* __restrict__ sv){
    int n=blockIdx.x;
    __shared__ float sin_[D];
    __shared__ float hid[SEH];
    int t=threadIdx.x;
    sin_[t]=sm[n*D+t];
    __syncthreads();
    if(t<SEH){
        float a=0.f;
        for(int c=0;c<D;c++) a+=sin_[c]*se1[c*SEH+t];
        hid[t]=gelu_f(a);
    }
    __syncthreads();
    float a=0.f;
    for(int j=0;j<SEH;j++) a+=hid[j]*se2[j*D+t];
    sv[n*D+t]=1.f/(1.f+expf(-a));
}

// ---------------- fma2 GEMM (pwconv only) ----------------
__global__ void __launch_bounds__(256,2) k_gemm(const float* __restrict__ Ab,
        const float* __restrict__ Bb, const float* __restrict__ aux,
        float* __restrict__ Cb, int ldb, int P){
    __shared__ float As[16][132];
    __shared__ float Bs[16][132];
    int tid=threadIdx.x;
    int m0=blockIdx.y*128, n0=blockIdx.x*128;
    long off=(long)blockIdx.z*256*P;
    const float* Bp=Bb+off;
    float* Cp=Cb+off;
    const float* svp=aux+blockIdx.z*256;
    ull acc[8][4];
    #pragma unroll
    for(int i=0;i<8;i++)
        #pragma unroll
        for(int j=0;j<4;j++) acc[i][j]=0ull;
    int ty=tid>>4, tx=tid&15;
    for(int k0=0;k0<256;k0+=16){
        #pragma unroll
        for(int l=0;l<2;l++){
            int e=tid+l*256; int row=e>>2, kc=(e&3)*4;
            float4 a4=*(const float4*)&Ab[(long)(m0+row)*256+k0+kc];
            float4 s4=*(const float4*)&svp[k0+kc];
            a4.x*=s4.x; a4.y*=s4.y; a4.z*=s4.z; a4.w*=s4.w;
            As[kc+0][row]=a4.x; As[kc+1][row]=a4.y;
            As[kc+2][row]=a4.z; As[kc+3][row]=a4.w;
        }
        #pragma unroll
        for(int l=0;l<2;l++){
            int e=tid+l*256; int kk=e>>5, nn=(e&31)*4;
            int col=n0+nn;
            float4 b4;
            const float* brow=&Bp[(long)(k0+kk)*ldb];
            if(col+3<P) b4=*(const float4*)&brow[col];
            else{
                b4.x=(col  <P)?brow[col  ]:0.f;
                b4.y=(col+1<P)?brow[col+1]:0.f;
                b4.z=(col+2<P)?brow[col+2]:0.f;
                b4.w=(col+3<P)?brow[col+3]:0.f;
            }
            *(float4*)&Bs[kk][nn]=b4;
        }
        __syncthreads();
        #pragma unroll
        for(int kk=0;kk<16;kk++){
            float4 a0=*(const float4*)&As[kk][ty*8];
            float4 a1=*(const float4*)&As[kk][ty*8+4];
            const ull* bp=(const ull*)&Bs[kk][tx*8];
            ull b2[4]={bp[0],bp[1],bp[2],bp[3]};
            float av[8]={a0.x,a0.y,a0.z,a0.w,a1.x,a1.y,a1.z,a1.w};
            #pragma unroll
            for(int i=0;i<8;i++){
                ull a2=pk2(av[i]);
                #pragma unroll
                for(int j=0;j<4;j++) fma2(acc[i][j],a2,b2[j]);
            }
        }
        __syncthreads();
    }
    #pragma unroll
    for(int i=0;i<8;i++){
        int m=ty*8+i;
        float o[8];
        #pragma unroll
        for(int j=0;j<4;j++){ float2 t2=upk(acc[i][j]); o[2*j]=t2.x; o[2*j+1]=t2.y; }
        int n=n0+tx*8;
        float* dst=&Cp[(long)(m0+m)*P+n];
        #pragma unroll
        for(int j=0;j<8;j++) if(n+j<P) dst[j]=o[j];
    }
}

// ---------------- residual + maxpool ----------------
__global__ void k_respool(const float* __restrict__ xin, const float* __restrict__ z,
                          float* __restrict__ out, int Hin, int Hout){
    int o=blockIdx.x*blockDim.x+threadIdx.x;
    int total=NB*D*Hout*Hout;
    if(o>=total) return;
    int wo=o%Hout; int t=o/Hout;
    int ho=t%Hout; t/=Hout;
    const float* xp=xin+(long)t*Hin*Hin;
    const float* zp=z  +(long)t*Hin*Hin;
    float mx=-INFINITY;
    #pragma unroll
    for(int kh=0;kh<3;kh++){
        int hh=2*ho-1+kh;
        if(hh<0||hh>=Hin) continue;
        #pragma unroll
        for(int kw=0;kw<3;kw++){
            int ww=2*wo-1+kw;
            if(ww<0||ww>=Hin) continue;
            mx=fmaxf(mx,xp[hh*Hin+ww]+zp[hh*Hin+ww]);
        }
    }
    out[o]=mx;
}

// ---------------- gattn stage 1 ----------------
__global__ void k_gattn1(){
    float* X=dsm;
    float* S=dsm+98*260;
    int bg=blockIdx.x, chunk=blockIdx.y;
    int b=bg>>2, g=bg&3, nx=g>>1, ny=g&1;
    int tid=threadIdx.x;
    for(int e=tid;e<98*256;e+=256){
        int c=e&255, i=e>>8;
        int m=i/49, rr=i%49, w1=rr/7, w2=rr%7;
        int n=b*2+m;
        X[i*260+c]=g_xg2[(((long)n*256+c)*14 + (nx*7+w1))*14 + (ny*7+w2)];
    }
    __syncthreads();
    int i0=chunk*26;
    int ni=min(26,98-i0);
    int npair=ni>>1;
    for(int t=tid;t<13*49;t+=256){
        int ip=t/49, jp=t%49;
        if(ip>=npair) continue;
        int i=i0+ip*2, j=jp*2;
        const ull* xi0=(const ull*)&X[i*260];
        const ull* xi1=(const ull*)&X[(i+1)*260];
        const ull* xj0=(const ull*)&X[j*260];
        const ull* xj1=(const ull*)&X[(j+1)*260];
        ull a00=0,a01=0,a10=0,a11=0;
        #pragma unroll 8
        for(int cp=0;cp<128;cp++){
            ull q0=xi0[cp],q1=xi1[cp],p0=xj0[cp],p1=xj1[cp];
            fma2(a00,q0,p0); fma2(a01,q0,p1); fma2(a10,q1,p0); fma2(a11,q1,p1);
        }
        float2 t00=upk(a00),t01=upk(a01),t10=upk(a10),t11=upk(a11);
        int il=i-i0;
        S[il*100+j]      =t00.x+t00.y;
        S[il*100+j+1]    =t01.x+t01.y;
        S[(il+1)*100+j]  =t10.x+t10.y;
        S[(il+1)*100+j+1]=t11.x+t11.y;
    }
    __syncthreads();
    int wd=tid>>5, lane=tid&31;
    for(int r=wd;r<ni;r+=8){
        float mx=-INFINITY;
        for(int j=lane;j<98;j+=32) mx=fmaxf(mx,S[r*100+j]);
        for(int o=16;o>0;o>>=1) mx=fmaxf(mx,__shfl_xor_sync(~0u,mx,o));
        float sum=0.f;
        for(int j=lane;j<98;j+=32){ float e=__expf(S[r*100+j]-mx); S[r*100+j]=e; sum+=e; }
        for(int o=16;o>0;o>>=1) sum+=__shfl_xor_sync(~0u,sum,o);
        float inv=0.0625f/sum;
        float* gs=&g_S[((long)bg*98 + i0+r)*98];
        for(int j=lane;j<98;j+=32) gs[j]=S[r*100+j]*inv;
    }
}

// ---------------- gattn stage 2 ----------------
__global__ void k_gattn2(){
    float* X=dsm;
    float* Ssh=dsm+98*260;
    int bg=blockIdx.x, chunk=blockIdx.y;
    int b=bg>>2, g=bg&3, nx=g>>1, ny=g&1;
    int tid=threadIdx.x;
    for(int e=tid;e<98*256;e+=256){
        int c=e&255, i=e>>8;
        int m=i/49, rr=i%49, w1=rr/7, w2=rr%7;
        int n=b*2+m;
        X[i*260+c]=g_xg2[(((long)n*256+c)*14 + (nx*7+w1))*14 + (ny*7+w2)];
    }
    int i0=chunk*26;
    int ni=min(26,98-i0);
    for(int e=tid;e<ni*98;e+=256){
        int r=e/98, j=e%98;
        Ssh[r*100+j]=g_S[((long)bg*98 + i0+r)*98 + j];
    }
    __syncthreads();
    int npair=ni>>1;
    for(int t=tid;t<13*64;t+=256){
        int ip=t>>6, cq=t&63;
        if(ip>=npair) continue;
        int i=i0+2*ip, c=cq*4;
        ull a00=0,a01=0,a10=0,a11=0;
        const float* S0=&Ssh[(2*ip)*100];
        const float* S1=&Ssh[(2*ip+1)*100];
        for(int j=0;j<98;j++){
            ull s0=pk2(S0[j]), s1=pk2(S1[j]);
            const ull* vp=(const ull*)&X[j*260+c];
            ull v0=vp[0], v1=vp[1];
            fma2(a00,s0,v0); fma2(a01,s0,v1);
            fma2(a10,s1,v0); fma2(a11,s1,v1);
        }
        float2 x00=upk(a00),x01=upk(a01),x10=upk(a10),x11=upk(a11);
        long basep=((long)bg*98+i)*256+c;
        *(float4*)&g_gout[basep]    =make_float4(x00.x,x00.y,x01.x,x01.y);
        *(float4*)&g_gout[basep+256]=make_float4(x10.x,x10.y,x11.x,x11.y);
    }
}

// ---------------- mean over 4 groups ----------------
__global__ void k_qmean(){
    int o=blockIdx.x*blockDim.x+threadIdx.x;
    if(o>=8*NTOK*D) return;
    int c=o&255; int t=o>>8; int i=t%NTOK; int b=t/NTOK;
    float a=0.f;
    for(int g=0;g<4;g++) a+=g_gout[(((long)(b*4+g)*NTOK)+i)*D+c];
    g_qglob[o]=a*0.25f;
}

// ---------------- RPE bias gather ----------------
__global__ void k_bias(const float* __restrict__ rpe){
    int o=blockIdx.x*blockDim.x+threadIdx.x;
    if(o>=NH*NTOK*NTOK) return;
    int j=o%NTOK; int t=o/NTOK; int i=t%NTOK; int h=t/NTOK;
    int mi=i/49, ri=i%49, ai=ri/7, bi=ri%7;
    int mj=j/49, rj=j%49, aj=rj/7, bj=rj%7;
    int idx=(mi-mj+1)*169 + (ai-aj+6)*13 + (bi-bj+6);
    g_biasb[o]=rpe[idx*NH+h];
}

// ---------------- host ----------------
extern "C" void kernel_launch(void* const* d_in, const int* in_sizes, int n_in,
                              void* d_out, int out_size){
    (void)in_sizes; (void)n_in; (void)out_size;
    const float* x       =(const float*)d_in[0];
    const float* qkv_w   =(const float*)d_in[1];
    const float* qkv_b   =(const float*)d_in[2];
    const float* to_out_w=(const float*)d_in[3];
    const float* rpe     =(const float*)d_in[4];
    const float* fe1_dw  =(const float*)d_in[5];
    const float* fe1_se1 =(const float*)d_in[6];
    const float* fe1_se2 =(const float*)d_in[7];
    const float* fe1_pw  =(const float*)d_in[8];
    const float* fe2_dw  =(const float*)d_in[9];
    const float* fe2_se1 =(const float*)d_in[10];
    const float* fe2_se2 =(const float*)d_in[11];
    const float* fe2_pw  =(const float*)d_in[12];
    float* outp=(float*)d_out;

    float *xg0,*yb,*zb,*xg1,*xg2,*smean,*svec,*aout;
    __nv_bfloat16 *wqh,*wql,*woh,*wol;
    cudaGetSymbolAddress((void**)&xg0,  g_xg0);
    cudaGetSymbolAddress((void**)&yb,   g_y);
    cudaGetSymbolAddress((void**)&zb,   g_z);
    cudaGetSymbolAddress((void**)&xg1,  g_xg1);
    cudaGetSymbolAddress((void**)&xg2,  g_xg2);
    cudaGetSymbolAddress((void**)&smean,g_smean);
    cudaGetSymbolAddress((void**)&svec, g_svec);
    cudaGetSymbolAddress((void**)&aout, g_aout);
    cudaGetSymbolAddress((void**)&wqh,  g_Wqh);
    cudaGetSymbolAddress((void**)&wql,  g_Wql);
    cudaGetSymbolAddress((void**)&woh,  g_Woh);
    cudaGetSymbolAddress((void**)&wol,  g_Wol);

    const int GATTN_SMEM=(98*260 + 26*100)*4;
    const int WATTN_SMEM=WSM_HALVES*2;   // 104960 B
    cudaFuncSetAttribute(k_gattn1, cudaFuncAttributeMaxDynamicSharedMemorySize, GATTN_SMEM);
    cudaFuncSetAttribute(k_gattn2, cudaFuncAttributeMaxDynamicSharedMemorySize, GATTN_SMEM);
    cudaFuncSetAttribute(k_wattn,  cudaFuncAttributeMaxDynamicSharedMemorySize, WATTN_SMEM);

    k_prep_w<<<(512*256+255)/256,256>>>(qkv_w, wqh, wql, 512);
    k_prep_w<<<(256*256+255)/256,256>>>(to_out_w, woh, wol, 256);

    k_rearrange<<<(NB*D*H1*H1+255)/256,256>>>(x);
    // FE1
    k_dwconv_gelu<<<(NB*D*H1*H1/4+255)/256,256>>>(xg0, fe1_dw, yb, H1);
    k_hwmean<<<NB*D,256>>>(yb, smean, H1);
    k_se<<<NB,256>>>(smean, fe1_se1, fe1_se2, svec);
    k_gemm<<<dim3(25,2,NB),256>>>(fe1_pw, yb, svec, zb, H1*H1, H1*H1);
    k_respool<<<(NB*D*H2*H2+255)/256,256>>>(xg0, zb, xg1, H1, H2);
    // FE2
    k_dwconv_gelu<<<(NB*D*H2*H2/4+255)/256,256>>>(xg1, fe2_dw, yb, H2);
    k_hwmean<<<NB*D,256>>>(yb, smean, H2);
    k_se<<<NB,256>>>(smean, fe2_se1, fe2_se2, svec);
    k_gemm<<<dim3(7,2,NB),256>>>(fe2_pw, yb, svec, zb, H2*H2, H2*H2);
    k_respool<<<(NB*D*H3*H3+255)/256,256>>>(xg1, zb, xg2, H2, H3);
    // global attention
    k_gattn1<<<dim3(32,4),256,GATTN_SMEM>>>();
    k_gattn2<<<dim3(32,4),256,GATTN_SMEM>>>();
    k_qmean<<<(8*NTOK*D+255)/256,256>>>();
    // window path
    k_mmagemm<<<dim3(4,MROWS/128),256>>>(x, wqh, wql, qkv_b, nullptr, 0);
    k_bias<<<(NH*NTOK*NTOK+255)/256,256>>>(rpe);
    k_wattn<<<NWIN*NH,256,WATTN_SMEM>>>();
    k_mmagemm<<<dim3(2,MROWS/128),256>>>(aout, woh, wol, nullptr, outp, 1);
}